// round 15
// baseline (speedup 1.0000x reference)
#include <cuda_runtime.h>
#include <cuda_bf16.h>
#include <stdint.h>
#include <math.h>

#define BB 8
#define NN 4096

typedef unsigned long long ull;

__device__ __forceinline__ ull dup2(float x) {
    ull r; asm("mov.b64 %0, {%1, %1};" : "=l"(r) : "f"(x)); return r;
}
__device__ __forceinline__ void unpack2(ull v, float& x, float& y) {
    asm("mov.b64 {%0, %1}, %2;" : "=f"(x), "=f"(y) : "l"(v));
}
__device__ __forceinline__ void fma2(ull& d, ull a, ull b) {
    asm("fma.rn.f32x2 %0, %1, %2, %0;" : "+l"(d) : "l"(a), "l"(b));
}

__device__ __forceinline__ unsigned smem_u32(const void* p) {
    unsigned a;
    asm("{ .reg .u64 t; cvta.to.shared.u64 t, %1; cvt.u32.u64 %0, t; }" : "=r"(a) : "l"(p));
    return a;
}
__device__ __forceinline__ void ldsm4(unsigned* r, unsigned addr) {
    asm volatile("ldmatrix.sync.aligned.m8n8.x4.shared.b16 {%0,%1,%2,%3}, [%4];"
        : "=r"(r[0]), "=r"(r[1]), "=r"(r[2]), "=r"(r[3]) : "r"(addr));
}
__device__ __forceinline__ void ldsm4t(unsigned* r, unsigned addr) {
    asm volatile("ldmatrix.sync.aligned.m8n8.x4.trans.shared.b16 {%0,%1,%2,%3}, [%4];"
        : "=r"(r[0]), "=r"(r[1]), "=r"(r[2]), "=r"(r[3]) : "r"(addr));
}
__device__ __forceinline__ void mma_bf16(float* c, const unsigned* a, const unsigned* b) {
    asm volatile("mma.sync.aligned.m16n8k16.row.col.f32.bf16.bf16.f32 "
        "{%0,%1,%2,%3}, {%4,%5,%6,%7}, {%8,%9}, {%0,%1,%2,%3};"
        : "+f"(c[0]), "+f"(c[1]), "+f"(c[2]), "+f"(c[3])
        : "r"(a[0]), "r"(a[1]), "r"(a[2]), "r"(a[3]), "r"(b[0]), "r"(b[1]));
}
__device__ __forceinline__ void cpa16(unsigned s, const void* g) {
    asm volatile("cp.async.ca.shared.global [%0], [%1], 16;" :: "r"(s), "l"(g));
}
#define CP_COMMIT() asm volatile("cp.async.commit_group;" ::: "memory")
#define CP_WAIT0() asm volatile("cp.async.wait_group 0;" ::: "memory")
#define CP_WAIT1() asm volatile("cp.async.wait_group 1;" ::: "memory")

// packed f32x2 exp
__device__ __forceinline__ void fexp2x(float x0, float x1, float& r0, float& r1) {
    ull x; asm("mov.b64 %0, {%1, %2};" : "=l"(x) : "f"(x0), "f"(x1));
    ull y; asm("mul.rn.f32x2 %0, %1, %2;" : "=l"(y) : "l"(x), "l"(dup2(1.4426950408889634f)));
    ull tt; asm("add.rn.f32x2 %0, %1, %2;" : "=l"(tt) : "l"(y), "l"(dup2(12582912.0f)));
    ull n; asm("add.rn.f32x2 %0, %1, %2;" : "=l"(n) : "l"(tt), "l"(dup2(-12582912.0f)));
    ull f = y; fma2(f, n, dup2(-1.0f));
    ull p = dup2(9.6181291076e-3f);  fma2(p, dup2(1.3333558146e-3f), f);
    ull p2 = dup2(5.5504108664e-2f); fma2(p2, p, f);
    ull p3 = dup2(2.4022650696e-1f); fma2(p3, p2, f);
    ull p4 = dup2(6.9314718056e-1f); fma2(p4, p3, f);
    ull p5 = dup2(1.0f);             fma2(p5, p4, f);
    unsigned i0, i1;
    asm("mov.b64 {%0, %1}, %2;" : "=r"(i0), "=r"(i1) : "l"(tt));
    float s0 = __uint_as_float((i0 + 127u) << 23);
    float s1 = __uint_as_float((i1 + 127u) << 23);
    float q0, q1; unpack2(p5, q0, q1);
    r0 = q0 * s0; r1 = q1 * s1;
}

__device__ __forceinline__ void fma2s(ull& d, ull a, ull b) { fma2(d, a, b); }

__device__ __forceinline__ void split_bf16(float v, __nv_bfloat16& h, __nv_bfloat16& l) {
    h = __float2bfloat16(v);
    l = __float2bfloat16(v - __bfloat162float(h));
}

// ---------------- scratch ----------------
__device__ float g_bqk[256];
__device__ float g_bout[512];
__device__ float g_qk[(size_t)BB * 128 * NN];            // rows 64-127: k1 fp32
__device__ __nv_bfloat16 g_E2[(size_t)BB * NN * NN];
__device__ float g_Zinv[BB * NN];
__device__ float g_Gp[BB * 8 * 64 * 64];
__device__ float g_A[BB * 64 * 64];
__device__ __nv_bfloat16 g_Wh[256 * 1024];
__device__ __nv_bfloat16 g_Wl[256 * 1024];
__device__ __nv_bfloat16 g_Xh[(size_t)BB * NN * 1024];
__device__ __nv_bfloat16 g_Xl[(size_t)BB * NN * 1024];
__device__ __nv_bfloat16 g_QKTh[(size_t)BB * NN * 128];
__device__ __nv_bfloat16 g_QKTl[(size_t)BB * NN * 128];
__device__ __nv_bfloat16 g_KZh[(size_t)BB * 64 * NN];
__device__ __nv_bfloat16 g_KZl[(size_t)BB * 64 * NN];
__device__ __nv_bfloat16 g_OSh[(size_t)BB * 128 * NN];
__device__ __nv_bfloat16 g_OSl[(size_t)BB * 128 * NN];
__device__ __nv_bfloat16 g_WCh[512 * 128];
__device__ __nv_bfloat16 g_WCl[512 * 128];
__device__ __nv_bfloat16 g_CH[(size_t)BB * 128 * NN];
__device__ __nv_bfloat16 g_CL[(size_t)BB * 128 * NN];

// ---------------- fused weight folding + bf16 split ----------------
__global__ void fold_qkw(const float* __restrict__ wt, const float* __restrict__ wb,
                         const float* __restrict__ sw1, const float* __restrict__ sw2,
                         const float* __restrict__ cwq, const float* __restrict__ cwk) {
    int idx = blockIdx.x * blockDim.x + threadIdx.x;
    int j = idx >> 9, c = idx & 511;
    const float* wrow; int uoff;
    if (j < 64)       { wrow = sw1 + j * 256;        uoff = 0;   }
    else if (j < 128) { wrow = sw2 + (j - 64) * 256; uoff = 0;   }
    else if (j < 192) { wrow = cwq + (j - 128) * 256; uoff = 256; }
    else              { wrow = cwk + (j - 192) * 256; uoff = 256; }
    float at = 0.f, ab = 0.f;
    #pragma unroll 8
    for (int u = 0; u < 256; ++u) {
        float w = wrow[u];
        at = fmaf(w, wt[(uoff + u) * 512 + c], at);
        ab = fmaf(w, wb[(uoff + u) * 512 + c], ab);
    }
    __nv_bfloat16 h, l;
    split_bf16(at, h, l);
    g_Wh[j * 1024 + c] = h; g_Wl[j * 1024 + c] = l;
    split_bf16(ab, h, l);
    g_Wh[j * 1024 + 512 + c] = h; g_Wl[j * 1024 + 512 + c] = l;
}

__global__ void fold_outc(const float* __restrict__ fw, const float* __restrict__ swo,
                          const float* __restrict__ cwo) {
    int idx = blockIdx.x * blockDim.x + threadIdx.x;
    int o = idx >> 7, t = idx & 127;
    float acc = 0.f;
    if (t < 64) {
        #pragma unroll 8
        for (int u = 0; u < 256; ++u)
            acc = fmaf(fw[o * 512 + u], swo[u * 64 + t], acc);
    } else {
        int r = t - 64;
        #pragma unroll 8
        for (int u = 0; u < 256; ++u)
            acc = fmaf(fw[o * 512 + 256 + u], cwo[u * 64 + r], acc);
    }
    __nv_bfloat16 h, l; split_bf16(acc, h, l);
    g_WCh[idx] = h; g_WCl[idx] = l;
}

__global__ void fold_bias(const float* __restrict__ bt, const float* __restrict__ bb,
                          const float* __restrict__ sb1, const float* __restrict__ sb2,
                          const float* __restrict__ cbq, const float* __restrict__ cbk,
                          const float* __restrict__ fw,  const float* __restrict__ sbo,
                          const float* __restrict__ cbo, const float* __restrict__ fb,
                          const float* __restrict__ sw1, const float* __restrict__ sw2,
                          const float* __restrict__ cwq, const float* __restrict__ cwk) {
    int t = threadIdx.x;   // 512
    if (t < 256) {
        const float* wrow; int uoff; float ob;
        int j = t;
        if (j < 64)       { wrow = sw1 + j * 256;        uoff = 0;   ob = sb1[j];       }
        else if (j < 128) { wrow = sw2 + (j - 64) * 256; uoff = 0;   ob = sb2[j - 64];  }
        else if (j < 192) { wrow = cwq + (j - 128) * 256; uoff = 256; ob = cbq[j - 128]; }
        else              { wrow = cwk + (j - 192) * 256; uoff = 256; ob = cbk[j - 192]; }
        float s = ob;
        for (int u = 0; u < 256; ++u)
            s = fmaf(wrow[u], bt[uoff + u] + bb[uoff + u], s);
        g_bqk[j] = s;
    }
    float s2 = fb[t];
    for (int u = 0; u < 256; ++u) {
        s2 = fmaf(fw[t * 512 + u],       sbo[u], s2);
        s2 = fmaf(fw[t * 512 + 256 + u], cbo[u], s2);
    }
    g_bout[t] = s2;
}

__global__ void conv_x(const float* __restrict__ top, const float* __restrict__ bot) {
    __shared__ float sh[32][33];
    int b = blockIdx.z;
    int c0 = blockIdx.y * 32;
    int p0 = blockIdx.x * 32;
    const float* src = (c0 < 512) ? top : bot;
    int cs = c0 & 511;
    int tx = threadIdx.x, ty = threadIdx.y;
    #pragma unroll
    for (int k = 0; k < 4; ++k) {
        int i = ty + k * 8;
        sh[i][tx] = src[((size_t)(b * 512 + cs + i)) * NN + p0 + tx];
    }
    __syncthreads();
    #pragma unroll
    for (int k = 0; k < 4; ++k) {
        int i = ty + k * 8;
        float v = sh[tx][i];
        __nv_bfloat16 h, l; split_bf16(v, h, l);
        size_t o = ((size_t)(b * NN + p0 + i)) * 1024 + c0 + tx;
        g_Xh[o] = h; g_Xl[o] = l;
    }
}

// ---------------- qk GEMM via HMMA, K-chunk 64, single buffer, 2 CTAs/SM ----------------
#define TS (128 * 72 * 2)        // 18432 B per tile
#define QK3_SMEM (4 * TS)        // 73728 B, fits 2 CTAs/SM
__global__ void __launch_bounds__(256, 2) qk_tc3() {
    extern __shared__ __align__(16) char smem[];
    unsigned sb = smem_u32(smem);
    int t = threadIdx.x;
    int wid = t >> 5, lid = t & 31;
    int b = blockIdx.z;
    int j0 = blockIdx.y * 128;
    int p0 = blockIdx.x * 128;
    int wr = wid & 1;
    int wc = wid >> 1;

    const __nv_bfloat16* srcs[4] = {
        g_Wh + (size_t)j0 * 1024,
        g_Wl + (size_t)j0 * 1024,
        g_Xh + ((size_t)b * NN + p0) * 1024,
        g_Xl + ((size_t)b * NN + p0) * 1024
    };

    float c[4][4][4] = {};

    unsigned aAddr = sb + (unsigned)((wr * 64 + (lid & 15)) * 144 + (lid >> 4) * 16);
    unsigned bAddr = sb + 2 * TS +
        (unsigned)((wc * 32 + ((lid >> 4) & 1) * 8 + (lid & 7)) * 144 + ((lid >> 3) & 1) * 16);

    for (int ch = 0; ch < 16; ++ch) {
        int c0 = ch * 64;
        // load chunk (cross-CTA overlap hides this behind the co-resident CTA's compute)
        #pragma unroll
        for (int tile = 0; tile < 4; ++tile) {
            unsigned base = sb + tile * TS;
            const __nv_bfloat16* s = srcs[tile];
            #pragma unroll
            for (int rep = 0; rep < 4; ++rep) {
                int u = t + rep * 256;
                int r = u >> 3, q = u & 7;
                cpa16(base + r * 144 + q * 16, s + (size_t)r * 1024 + c0 + q * 8);
            }
        }
        CP_COMMIT();
        CP_WAIT0();
        __syncthreads();
        #pragma unroll
        for (int ks = 0; ks < 4; ++ks) {
            unsigned bh[2][4], bl[2][4];
            ldsm4(bh[0], bAddr + ks * 32);
            ldsm4(bh[1], bAddr + 16 * 144 + ks * 32);
            ldsm4(bl[0], bAddr + TS + ks * 32);
            ldsm4(bl[1], bAddr + TS + 16 * 144 + ks * 32);
            #pragma unroll
            for (int mt = 0; mt < 4; ++mt) {
                unsigned ah[4], al[4];
                ldsm4(ah, aAddr + mt * 2304 + ks * 32);
                ldsm4(al, aAddr + TS + mt * 2304 + ks * 32);
                #pragma unroll
                for (int nt = 0; nt < 4; ++nt) {
                    const unsigned* bhp = &bh[nt >> 1][(nt & 1) * 2];
                    const unsigned* blp = &bl[nt >> 1][(nt & 1) * 2];
                    mma_bf16(c[mt][nt], ah, bhp);
                    mma_bf16(c[mt][nt], ah, blp);
                    mma_bf16(c[mt][nt], al, bhp);
                }
            }
        }
        __syncthreads();
    }

    int g = lid >> 2, tig = lid & 3;
    if (blockIdx.y == 0) {
        // stage bf16 hi/lo transpose in smem, write QKT; k1 rows also fp32 to g_qk
        __nv_bfloat16* Th = (__nv_bfloat16*)smem;          // [128][136]
        __nv_bfloat16* Tl = Th + 128 * 136;
        #pragma unroll
        for (int mt = 0; mt < 4; ++mt) {
            int jrow = wr * 64 + mt * 16 + g;
            float b0 = g_bqk[jrow], b1 = g_bqk[jrow + 8];
            #pragma unroll
            for (int nt = 0; nt < 4; ++nt) {
                int p = wc * 32 + nt * 8 + tig * 2;
                float v0 = c[mt][nt][0] + b0;
                float v1 = c[mt][nt][1] + b0;
                float v2 = c[mt][nt][2] + b1;
                float v3 = c[mt][nt][3] + b1;
                __nv_bfloat16 h, l;
                split_bf16(v0, h, l); Th[p * 136 + jrow] = h;       Tl[p * 136 + jrow] = l;
                split_bf16(v1, h, l); Th[(p + 1) * 136 + jrow] = h; Tl[(p + 1) * 136 + jrow] = l;
                split_bf16(v2, h, l); Th[p * 136 + jrow + 8] = h;   Tl[p * 136 + jrow + 8] = l;
                split_bf16(v3, h, l); Th[(p + 1) * 136 + jrow + 8] = h; Tl[(p + 1) * 136 + jrow + 8] = l;
                if (wr == 1) {
                    size_t r0 = ((size_t)(b * 128 + jrow)) * NN;
                    size_t r1 = r0 + (size_t)8 * NN;
                    *(float2*)&g_qk[r0 + p0 + p] = {v0, v1};
                    *(float2*)&g_qk[r1 + p0 + p] = {v2, v3};
                }
            }
        }
        __syncthreads();
        #pragma unroll
        for (int rep = 0; rep < 8; ++rep) {
            int u = t + rep * 256;
            int r = u >> 4, q = u & 15;
            size_t dst = ((size_t)(b * NN + p0 + r)) * 128 + q * 8;
            *(uint4*)(g_QKTh + dst) = *(const uint4*)&Th[r * 136 + q * 8];
            *(uint4*)(g_QKTl + dst) = *(const uint4*)&Tl[r * 136 + q * 8];
        }
    } else {
        #pragma unroll
        for (int mt = 0; mt < 4; ++mt) {
            int jl = wr * 64 + mt * 16 + g;
            float b0 = g_bqk[128 + jl], b1 = g_bqk[128 + jl + 8];
            size_t r0 = ((size_t)(b * 128 + jl)) * NN;
            size_t r1 = r0 + (size_t)8 * NN;
            #pragma unroll
            for (int nt = 0; nt < 4; ++nt) {
                int pc = p0 + wc * 32 + nt * 8 + tig * 2;
                __nv_bfloat16 h0, l0, h1, l1;
                split_bf16(c[mt][nt][0] + b0, h0, l0);
                split_bf16(c[mt][nt][1] + b0, h1, l1);
                *(__nv_bfloat162*)&g_CH[r0 + pc] = {h0, h1};
                *(__nv_bfloat162*)&g_CL[r0 + pc] = {l0, l1};
                split_bf16(c[mt][nt][2] + b1, h0, l0);
                split_bf16(c[mt][nt][3] + b1, h1, l1);
                *(__nv_bfloat162*)&g_CH[r1 + pc] = {h0, h1};
                *(__nv_bfloat162*)&g_CL[r1 + pc] = {l0, l1};
            }
        }
    }
}

// ---------------- spatial pass A (HMMA + packed exp + fused Kz epilogue) ----------------
#define PAT 18432
#define PA_SMEM (6 * PAT + 2048 + 512)
__global__ void __launch_bounds__(256, 2) passA_tc() {
    extern __shared__ __align__(16) char smem[];
    unsigned sb = smem_u32(smem);
    int t = threadIdx.x;
    int wid = t >> 5, lid = t & 31;
    int b = blockIdx.y;
    int n0 = blockIdx.x * 128;
    int wr = wid & 1;
    int wc = wid >> 1;
    int g = lid >> 2, tig = lid & 3;

    #pragma unroll
    for (int rep = 0; rep < 4; ++rep) {
        int u = t + rep * 256;
        int r = u >> 3, q = u & 7;
        size_t src = ((size_t)b * NN + n0 + r) * 128 + q * 8;
        cpa16(sb + r * 144 + q * 16, g_QKTh + src);
        cpa16(sb + PAT + r * 144 + q * 16, g_QKTl + src);
    }
    #pragma unroll
    for (int rep = 0; rep < 4; ++rep) {
        int u = t + rep * 256;
        int r = u >> 3, q = u & 7;
        size_t src = ((size_t)b * NN + r) * 128 + 64 + q * 8;
        cpa16(sb + 2 * PAT + r * 144 + q * 16, g_QKTh + src);
        cpa16(sb + 3 * PAT + r * 144 + q * 16, g_QKTl + src);
    }
    CP_COMMIT();

    unsigned aAddrH = sb + (unsigned)((wr * 64 + (lid & 15)) * 144 + (lid >> 4) * 16);

    float zacc[8] = {};
    size_t ebase = ((size_t)b) << 24;

    for (int ch = 0; ch < 32; ++ch) {
        int m0 = ch * 128;
        if (ch + 1 < 32) {
            unsigned kb = 2 * PAT + ((ch + 1) & 1) * 2 * PAT;
            int m1 = (ch + 1) * 128;
            #pragma unroll
            for (int rep = 0; rep < 4; ++rep) {
                int u = t + rep * 256;
                int r = u >> 3, q = u & 7;
                size_t src = ((size_t)b * NN + m1 + r) * 128 + 64 + q * 8;
                cpa16(sb + kb + r * 144 + q * 16, g_QKTh + src);
                cpa16(sb + kb + PAT + r * 144 + q * 16, g_QKTl + src);
            }
            CP_COMMIT();
            CP_WAIT1();
        } else {
            CP_WAIT0();
        }
        __syncthreads();
        unsigned kb = 2 * PAT + (ch & 1) * 2 * PAT;
        unsigned bAddrH = sb + kb +
            (unsigned)((wc * 32 + ((lid >> 4) & 1) * 8 + (lid & 7)) * 144 + ((lid >> 3) & 1) * 16);
        float c[4][4][4] = {};
        #pragma unroll
        for (int ks = 0; ks < 4; ++ks) {
            unsigned bh[2][4], bl[2][4];
            ldsm4(bh[0], bAddrH + ks * 32);
            ldsm4(bh[1], bAddrH + 16 * 144 + ks * 32);
            ldsm4(bl[0], bAddrH + PAT + ks * 32);
            ldsm4(bl[1], bAddrH + PAT + 16 * 144 + ks * 32);
            #pragma unroll
            for (int mt = 0; mt < 4; ++mt) {
                unsigned ah[4], al[4];
                ldsm4(ah, aAddrH + mt * 2304 + ks * 32);
                ldsm4(al, aAddrH + PAT + mt * 2304 + ks * 32);
                #pragma unroll
                for (int nt = 0; nt < 4; ++nt) {
                    const unsigned* bhp = &bh[nt >> 1][(nt & 1) * 2];
                    const unsigned* blp = &bl[nt >> 1][(nt & 1) * 2];
                    mma_bf16(c[mt][nt], ah, bhp);
                    mma_bf16(c[mt][nt], ah, blp);
                    mma_bf16(c[mt][nt], al, bhp);
                }
            }
        }
        #pragma unroll
        for (int mt = 0; mt < 4; ++mt) {
            int n = n0 + wr * 64 + mt * 16 + g;
            #pragma unroll
            for (int nt = 0; nt < 4; ++nt) {
                int m = m0 + wc * 32 + nt * 8 + tig * 2;
                float e0, e1, e2, e3;
                fexp2x(c[mt][nt][0], c[mt][nt][1], e0, e1);
                fexp2x(c[mt][nt][2], c[mt][nt][3], e2, e3);
                __nv_bfloat162 v0 = {__float2bfloat16(e0), __float2bfloat16(e1)};
                __nv_bfloat162 v1 = {__float2bfloat16(e2), __float2bfloat16(e3)};
                *(__nv_bfloat162*)&g_E2[ebase + (size_t)n * NN + m] = v0;
                *(__nv_bfloat162*)&g_E2[ebase + (size_t)(n + 8) * NN + m] = v1;
                zacc[mt * 2] += e0 + e1;
                zacc[mt * 2 + 1] += e2 + e3;
            }
        }
        __syncthreads();
    }

    float* zp = (float*)(smem + 6 * PAT);
    float* zsm = (float*)(smem + 6 * PAT + 2048);
    #pragma unroll
    for (int s = 0; s < 8; ++s) {
        float v = zacc[s];
        v += __shfl_xor_sync(0xFFFFFFFF, v, 1);
        v += __shfl_xor_sync(0xFFFFFFFF, v, 2);
        if (tig == 0)
            zp[wc * 128 + wr * 64 + (s >> 1) * 16 + (s & 1) * 8 + g] = v;
    }
    __syncthreads();
    if (t < 128) {
        float s = zp[t] + zp[128 + t] + zp[256 + t] + zp[384 + t];
        float zi = 1.0f / s;
        g_Zinv[b * NN + n0 + t] = zi;
        zsm[t] = zi;
    }
    __syncthreads();

    #pragma unroll
    for (int rep = 0; rep < 8; ++rep) {
        int idx = t + rep * 256;
        int r = idx >> 5;
        int nq = (idx & 31) * 4;
        float4 k4 = *(const float4*)&g_qk[((size_t)(b * 128 + 64 + r)) * NN + n0 + nq];
        float v0 = k4.x * zsm[nq];
        float v1 = k4.y * zsm[nq + 1];
        float v2 = k4.z * zsm[nq + 2];
        float v3 = k4.w * zsm[nq + 3];
        __nv_bfloat16 h0, l0, h1, l1;
        size_t o = ((size_t)b * 64 + r) * NN + n0 + nq;
        split_bf16(v0, h0, l0); split_bf16(v1, h1, l1);
        *(__nv_bfloat162*)&g_KZh[o] = {h0, h1};
        *(__nv_bfloat162*)&g_KZl[o] = {l0, l1};
        split_bf16(v2, h0, l0); split_bf16(v3, h1, l1);
        *(__nv_bfloat162*)&g_KZh[o + 2] = {h0, h1};
        *(__nv_bfloat162*)&g_KZl[o + 2] = {l0, l1};
    }
}

// ---------------- spatial pass B ----------------
#define PBS 35840
#define PB_SMEM (2 * PBS)
__global__ void __launch_bounds__(256, 2) passB_tc() {
    extern __shared__ __align__(16) char smem[];
    unsigned sb = smem_u32(smem);
    int t = threadIdx.x;
    int wid = t >> 5, lid = t & 31;
    int b = blockIdx.y;
    int m0 = blockIdx.x * 128;
    int g = lid >> 2, tig = lid & 3;

    float c[4][2][4] = {};
    size_t ebase = ((size_t)b) << 24;

    {
        #pragma unroll
        for (int rep = 0; rep < 2; ++rep) {
            int u = t + rep * 256;
            int r = u >> 3, q = u & 7;
            size_t src = ((size_t)b * 64 + r) * NN + q * 8;
            cpa16(sb + r * 144 + q * 16, g_KZh + src);
            cpa16(sb + 9216 + r * 144 + q * 16, g_KZl + src);
        }
        #pragma unroll
        for (int rep = 0; rep < 4; ++rep) {
            int u = t + rep * 256;
            int r = u >> 4, q = u & 15;
            cpa16(sb + 18432 + r * 272 + q * 16, g_E2 + ebase + (size_t)r * NN + m0 + q * 8);
        }
        CP_COMMIT();
    }

    for (int ch = 0; ch < 64; ++ch) {
        if (ch + 1 < 64) {
            unsigned boff = ((ch + 1) & 1) * PBS;
            int n1 = (ch + 1) * 64;
            #pragma unroll
            for (int rep = 0; rep < 2; ++rep) {
                int u = t + rep * 256;
                int r = u >> 3, q = u & 7;
                size_t src = ((size_t)b * 64 + r) * NN + n1 + q * 8;
                cpa16(sb + boff + r * 144 + q * 16, g_KZh + src);
                cpa16(sb + boff + 9216 + r * 144 + q * 16, g_KZl + src);
            }
            #pragma unroll
            for (int rep = 0; rep < 4; ++rep) {
                int u = t + rep * 256;
                int r = u >> 4, q = u & 15;
                cpa16(sb + boff + 18432 + r * 272 + q * 16,
                      g_E2 + ebase + (size_t)(n1 + r) * NN + m0 + q * 8);
            }
            CP_COMMIT();
            CP_WAIT1();
        } else {
            CP_WAIT0();
        }
        __syncthreads();
        unsigned boff = (ch & 1) * PBS;
        unsigned aAddrH = sb + boff + (unsigned)(((lid & 15)) * 144 + (lid >> 4) * 16);
        unsigned eAddr = sb + boff + 18432 +
            (unsigned)(((lid & 7) + ((lid >> 3) & 1) * 8) * 272 + (wid * 16 + (lid >> 4) * 8) * 2);
        #pragma unroll
        for (int ks = 0; ks < 4; ++ks) {
            unsigned eb[4];
            ldsm4t(eb, eAddr + ks * 16 * 272);
            #pragma unroll
            for (int mt = 0; mt < 4; ++mt) {
                unsigned ah[4], al[4];
                ldsm4(ah, aAddrH + mt * 2304 + ks * 32);
                ldsm4(al, aAddrH + 9216 + mt * 2304 + ks * 32);
                #pragma unroll
                for (int nt = 0; nt < 2; ++nt) {
                    mma_bf16(c[mt][nt], ah, &eb[nt * 2]);
                    mma_bf16(c[mt][nt], al, &eb[nt * 2]);
                }
            }
        }
        __syncthreads();
    }

    #pragma unroll
    for (int mt = 0; mt < 4; ++mt) {
        int r = mt * 16 + g;
        size_t r0 = ((size_t)(b * 128 + r)) * NN;
        size_t r1 = r0 + (size_t)8 * NN;
        #pragma unroll
        for (int nt = 0; nt < 2; ++nt) {
            int m = m0 + wid * 16 + nt * 8 + tig * 2;
            __nv_bfloat16 h0, l0, h1, l1;
            split_bf16(c[mt][nt][0], h0, l0);
            split_bf16(c[mt][nt][1], h1, l1);
            *(__nv_bfloat162*)&g_OSh[r0 + m] = {h0, h1};
            *(__nv_bfloat162*)&g_OSl[r0 + m] = {l0, l1};
            split_bf16(c[mt][nt][2], h0, l0);
            split_bf16(c[mt][nt][3], h1, l1);
            *(__nv_bfloat162*)&g_OSh[r1 + m] = {h0, h1};
            *(__nv_bfloat162*)&g_OSl[r1 + m] = {l0, l1};
        }
    }
}

// ---------------- channel Gram via HMMA ----------------
__global__ void __launch_bounds__(128) chan_gram_tc() {
    __shared__ __align__(16) char csm[4 * 9216];
    unsigned sb = smem_u32(csm);
    int t = threadIdx.x;
    int wid = t >> 5, lid = t & 31;
    int b = blockIdx.y;
    int chunk = blockIdx.x;
    int wr = wid & 1, wc = wid >> 1;
    int g = lid >> 2, tig = lid & 3;

    unsigned aAddr = sb + (unsigned)((wr * 32 + (lid & 15)) * 144 + (lid >> 4) * 16);
    unsigned bAddr = sb + 2 * 9216 +
        (unsigned)((wc * 32 + ((lid >> 4) & 1) * 8 + (lid & 7)) * 144 + ((lid >> 3) & 1) * 16);

    float c[2][4][4] = {};

    for (int sub = 0; sub < 8; ++sub) {
        int n0 = chunk * 512 + sub * 64;
        __syncthreads();
        #pragma unroll
        for (int rep = 0; rep < 4; ++rep) {
            int u = t + rep * 128;
            int r = u >> 3, q = u & 7;
            size_t sq = ((size_t)(b * 128 + r)) * NN + n0 + q * 8;
            size_t sk = ((size_t)(b * 128 + 64 + r)) * NN + n0 + q * 8;
            *(uint4*)(csm + r * 144 + q * 16) = *(const uint4*)(g_CH + sq);
            *(uint4*)(csm + 9216 + r * 144 + q * 16) = *(const uint4*)(g_CL + sq);
            *(uint4*)(csm + 2 * 9216 + r * 144 + q * 16) = *(const uint4*)(g_CH + sk);
            *(uint4*)(csm + 3 * 9216 + r * 144 + q * 16) = *(const uint4*)(g_CL + sk);
        }
        __syncthreads();
        #pragma unroll
        for (int ks = 0; ks < 4; ++ks) {
            unsigned bh[2][4], bl[2][4];
            ldsm4(bh[0], bAddr + ks * 32);
            ldsm4(bh[1], bAddr + 16 * 144 + ks * 32);
            ldsm4(bl[0], bAddr + 9216 + ks * 32);
            ldsm4(bl[1], bAddr + 9216 + 16 * 144 + ks * 32);
            #pragma unroll
            for (int mt = 0; mt < 2; ++mt) {
                unsigned ah[4], al[4];
                ldsm4(ah, aAddr + mt * 2304 + ks * 32);
                ldsm4(al, aAddr + 9216 + mt * 2304 + ks * 32);
                #pragma unroll
                for (int nt = 0; nt < 4; ++nt) {
                    const unsigned* bhp = &bh[nt >> 1][(nt & 1) * 2];
                    const unsigned* blp = &bl[nt >> 1][(nt & 1) * 2];
                    mma_bf16(c[mt][nt], ah, bhp);
                    mma_bf16(c[mt][nt], ah, blp);
                    mma_bf16(c[mt][nt], al, bhp);
                }
            }
        }
    }

    float* gp = &g_Gp[(b * 8 + chunk) * 4096];
    #pragma unroll
    for (int mt = 0; mt < 2; ++mt) {
        int r = wr * 32 + mt * 16 + g;
        #pragma unroll
        for (int nt = 0; nt < 4; ++nt) {
            int s = wc * 32 + nt * 8 + tig * 2;
            *(float2*)&gp[r * 64 + s] = {c[mt][nt][0], c[mt][nt][1]};
            *(float2*)&gp[(r + 8) * 64 + s] = {c[mt][nt][2], c[mt][nt][3]};
        }
    }
}

__global__ void chan_softmax() {
    int r = blockIdx.x;
    int b = blockIdx.y;
    int s = threadIdx.x;
    __shared__ float red[64];
    float v = 0.f;
    #pragma unroll
    for (int ch = 0; ch < 8; ++ch)
        v += g_Gp[(b * 8 + ch) * 4096 + r * 64 + s];
    red[s] = v;
    __syncthreads();
    for (int off = 32; off >= 1; off >>= 1) {
        if (s < off) red[s] = fmaxf(red[s], red[s + off]);
        __syncthreads();
    }
    float mx = red[0];
    __syncthreads();
    float e = __expf(v - mx);
    red[s] = e;
    __syncthreads();
    for (int off = 32; off >= 1; off >>= 1) {
        if (s < off) red[s] += red[s + off];
        __syncthreads();
    }
    g_A[b * 4096 + r * 64 + s] = e / red[0];
}

__global__ void __launch_bounds__(256) chan_out() {
    int b = blockIdx.y;
    int p = blockIdx.x * 256 + threadIdx.x;
    __shared__ __align__(16) float As[64][64];
    #pragma unroll
    for (int k = 0; k < 16; ++k)
        (&As[0][0])[threadIdx.x + k * 256] = g_A[b * 4096 + threadIdx.x + k * 256];
    __syncthreads();
    float kreg[64];
    #pragma unroll
    for (int s = 0; s < 64; ++s) {
        size_t o = ((size_t)(b * 128 + 64 + s)) * NN + p;
        kreg[s] = __bfloat162float(g_CH[o]) + __bfloat162float(g_CL[o]);
    }
    ull kp2[32];
    #pragma unroll
    for (int s = 0; s < 32; ++s) {
        ull r; asm("mov.b64 %0, {%1, %2};" : "=l"(r) : "f"(kreg[2 * s]), "f"(kreg[2 * s + 1]));
        kp2[s] = r;
    }
    #pragma unroll 2
    for (int r = 0; r < 64; ++r) {
        ull acc = 0;
        const ull* arow = (const ull*)&As[r][0];
        #pragma unroll
        for (int s = 0; s < 32; ++s)
            fma2s(acc, arow[s], kp2[s]);
        float lo, hi;
        unpack2(acc, lo, hi);
        float v = lo + hi;
        __nv_bfloat16 h, l; split_bf16(v, h, l);
        size_t o = ((size_t)(b * 128 + 64 + r)) * NN + p;
        g_OSh[o] = h; g_OSl[o] = l;
    }
}

// ---------------- final GEMM via HMMA (3-pass) ----------------
#define FT_SMEM 139264
__global__ void __launch_bounds__(256) final_tc(float* __restrict__ out) {
    extern __shared__ __align__(16) char smem[];
    unsigned sb = smem_u32(smem);
    int t = threadIdx.x;
    int wid = t >> 5, lid = t & 31;
    int b = blockIdx.z;
    int o0 = blockIdx.y * 128;
    int p0 = blockIdx.x * 128;
    int wr = wid & 1, wc = wid >> 1;
    int g = lid >> 2, tig = lid & 3;

    #pragma unroll
    for (int rep = 0; rep < 8; ++rep) {
        int u = t + rep * 256;
        int r = u >> 4, q = u & 15;
        *(uint4*)(smem + r * 272 + q * 16) = *(const uint4*)(g_WCh + (size_t)(o0 + r) * 128 + q * 8);
        *(uint4*)(smem + 34816 + r * 272 + q * 16) = *(const uint4*)(g_WCl + (size_t)(o0 + r) * 128 + q * 8);
        size_t bs = ((size_t)(b * 128 + r)) * NN + p0 + q * 8;
        *(uint4*)(smem + 69632 + r * 272 + q * 16) = *(const uint4*)(g_OSh + bs);
        *(uint4*)(smem + 104448 + r * 272 + q * 16) = *(const uint4*)(g_OSl + bs);
    }
    __syncthreads();

    unsigned aAddr = sb + (unsigned)((wr * 64 + (lid & 15)) * 272 + (lid >> 4) * 16);
    unsigned eAddr = sb + 69632 +
        (unsigned)(((lid & 7) + ((lid >> 3) & 1) * 8) * 272 + (wc * 32 + (lid >> 4) * 8) * 2);

    float c[4][4][4] = {};
    #pragma unroll
    for (int ks = 0; ks < 8; ++ks) {
        unsigned bh[2][4], bl[2][4];
        ldsm4t(bh[0], eAddr + ks * 16 * 272);
        ldsm4t(bh[1], eAddr + ks * 16 * 272 + 32);
        ldsm4t(bl[0], eAddr + 34816 + ks * 16 * 272);
        ldsm4t(bl[1], eAddr + 34816 + ks * 16 * 272 + 32);
        #pragma unroll
        for (int mt = 0; mt < 4; ++mt) {
            unsigned ah[4], al[4];
            ldsm4(ah, aAddr + mt * 16 * 272 + ks * 32);
            ldsm4(al, aAddr + 34816 + mt * 16 * 272 + ks * 32);
            #pragma unroll
            for (int nt = 0; nt < 4; ++nt) {
                const unsigned* bhp = &bh[nt >> 1][(nt & 1) * 2];
                const unsigned* blp = &bl[nt >> 1][(nt & 1) * 2];
                mma_bf16(c[mt][nt], ah, bhp);
                mma_bf16(c[mt][nt], ah, blp);
                mma_bf16(c[mt][nt], al, bhp);
            }
        }
    }

    #pragma unroll
    for (int mt = 0; mt < 4; ++mt) {
        int o = o0 + wr * 64 + mt * 16 + g;
        float b0 = g_bout[o], b1 = g_bout[o + 8];
        size_t r0 = ((size_t)(b * 512 + o)) * NN;
        size_t r1 = r0 + (size_t)8 * NN;
        #pragma unroll
        for (int nt = 0; nt < 4; ++nt) {
            int pc = p0 + wc * 32 + nt * 8 + tig * 2;
            float2 v0 = {c[mt][nt][0] + b0, c[mt][nt][1] + b0};
            float2 v1 = {c[mt][nt][2] + b1, c[mt][nt][3] + b1};
            *(float2*)&out[r0 + pc] = v0;
            *(float2*)&out[r1 + pc] = v1;
        }
    }
}

// ---------------- launch ----------------
extern "C" void kernel_launch(void* const* d_in, const int* in_sizes, int n_in,
                              void* d_out, int out_size) {
    const float* top  = (const float*)d_in[0];
    const float* bot  = (const float*)d_in[1];
    const float* wt   = (const float*)d_in[2];
    const float* bt   = (const float*)d_in[3];
    const float* wb   = (const float*)d_in[4];
    const float* bb   = (const float*)d_in[5];
    const float* s_w1 = (const float*)d_in[6];
    const float* s_b1 = (const float*)d_in[7];
    const float* s_w2 = (const float*)d_in[8];
    const float* s_b2 = (const float*)d_in[9];
    const float* s_wo = (const float*)d_in[10];
    const float* s_bo = (const float*)d_in[11];
    const float* c_wq = (const float*)d_in[12];
    const float* c_bq = (const float*)d_in[13];
    const float* c_wk = (const float*)d_in[14];
    const float* c_bk = (const float*)d_in[15];
    const float* c_wo = (const float*)d_in[16];
    const float* c_bo = (const float*)d_in[17];
    const float* f_w  = (const float*)d_in[18];
    const float* f_b  = (const float*)d_in[19];
    float* out = (float*)d_out;

    static cudaStream_t s2 = 0;
    static cudaEvent_t evStart = 0, evPre = 0, evQk = 0, evChan = 0;
    if (!s2) {
        cudaStreamCreateWithFlags(&s2, cudaStreamNonBlocking);
        cudaEventCreateWithFlags(&evStart, cudaEventDisableTiming);
        cudaEventCreateWithFlags(&evPre, cudaEventDisableTiming);
        cudaEventCreateWithFlags(&evQk, cudaEventDisableTiming);
        cudaEventCreateWithFlags(&evChan, cudaEventDisableTiming);
        cudaFuncSetAttribute(qk_tc3, cudaFuncAttributeMaxDynamicSharedMemorySize, QK3_SMEM);
        cudaFuncSetAttribute(passA_tc, cudaFuncAttributeMaxDynamicSharedMemorySize, PA_SMEM);
        cudaFuncSetAttribute(passB_tc, cudaFuncAttributeMaxDynamicSharedMemorySize, PB_SMEM);
        cudaFuncSetAttribute(final_tc, cudaFuncAttributeMaxDynamicSharedMemorySize, FT_SMEM);
    }

    cudaEventRecord(evStart, 0);
    cudaStreamWaitEvent(s2, evStart, 0);

    fold_qkw<<<512, 256>>>(wt, wb, s_w1, s_w2, c_wq, c_wk);
    fold_bias<<<1, 512>>>(bt, bb, s_b1, s_b2, c_bq, c_bk, f_w, s_bo, c_bo, f_b,
                          s_w1, s_w2, c_wq, c_wk);
    conv_x<<<dim3(128, 32, 8), dim3(32, 8), 0, s2>>>(top, bot);
    cudaEventRecord(evPre, s2);
    cudaStreamWaitEvent(0, evPre, 0);

    qk_tc3<<<dim3(32, 2, 8), 256, QK3_SMEM>>>();
    cudaEventRecord(evQk, 0);

    cudaStreamWaitEvent(s2, evQk, 0);
    fold_outc<<<256, 256, 0, s2>>>(f_w, s_wo, c_wo);
    chan_gram_tc<<<dim3(8, 8), 128, 0, s2>>>();
    chan_softmax<<<dim3(64, 8), 64, 0, s2>>>();
    chan_out<<<dim3(16, 8), 256, 0, s2>>>();
    cudaEventRecord(evChan, s2);

    passA_tc<<<dim3(32, 8), 256, PA_SMEM>>>();
    passB_tc<<<dim3(32, 8), 256, PB_SMEM>>>();

    cudaStreamWaitEvent(0, evChan, 0);
    final_tc<<<dim3(32, 4, 8), 256, FT_SMEM>>>(out);
}

// round 16
// speedup vs baseline: 1.4926x; 1.4926x over previous
#include <cuda_runtime.h>
#include <cuda_bf16.h>
#include <stdint.h>
#include <math.h>

#define BB 8
#define NN 4096

typedef unsigned long long ull;

__device__ __forceinline__ ull dup2(float x) {
    ull r; asm("mov.b64 %0, {%1, %1};" : "=l"(r) : "f"(x)); return r;
}
__device__ __forceinline__ void unpack2(ull v, float& x, float& y) {
    asm("mov.b64 {%0, %1}, %2;" : "=f"(x), "=f"(y) : "l"(v));
}
__device__ __forceinline__ void fma2(ull& d, ull a, ull b) {
    asm("fma.rn.f32x2 %0, %1, %2, %0;" : "+l"(d) : "l"(a), "l"(b));
}

__device__ __forceinline__ unsigned smem_u32(const void* p) {
    unsigned a;
    asm("{ .reg .u64 t; cvta.to.shared.u64 t, %1; cvt.u32.u64 %0, t; }" : "=r"(a) : "l"(p));
    return a;
}
__device__ __forceinline__ void ldsm4(unsigned* r, unsigned addr) {
    asm volatile("ldmatrix.sync.aligned.m8n8.x4.shared.b16 {%0,%1,%2,%3}, [%4];"
        : "=r"(r[0]), "=r"(r[1]), "=r"(r[2]), "=r"(r[3]) : "r"(addr));
}
__device__ __forceinline__ void ldsm4t(unsigned* r, unsigned addr) {
    asm volatile("ldmatrix.sync.aligned.m8n8.x4.trans.shared.b16 {%0,%1,%2,%3}, [%4];"
        : "=r"(r[0]), "=r"(r[1]), "=r"(r[2]), "=r"(r[3]) : "r"(addr));
}
__device__ __forceinline__ void mma_bf16(float* c, const unsigned* a, const unsigned* b) {
    asm volatile("mma.sync.aligned.m16n8k16.row.col.f32.bf16.bf16.f32 "
        "{%0,%1,%2,%3}, {%4,%5,%6,%7}, {%8,%9}, {%0,%1,%2,%3};"
        : "+f"(c[0]), "+f"(c[1]), "+f"(c[2]), "+f"(c[3])
        : "r"(a[0]), "r"(a[1]), "r"(a[2]), "r"(a[3]), "r"(b[0]), "r"(b[1]));
}
__device__ __forceinline__ void cpa16(unsigned s, const void* g) {
    asm volatile("cp.async.ca.shared.global [%0], [%1], 16;" :: "r"(s), "l"(g));
}
#define CP_COMMIT() asm volatile("cp.async.commit_group;" ::: "memory")
#define CP_WAIT0() asm volatile("cp.async.wait_group 0;" ::: "memory")
#define CP_WAIT1() asm volatile("cp.async.wait_group 1;" ::: "memory")

// packed f32x2 exp
__device__ __forceinline__ void fexp2x(float x0, float x1, float& r0, float& r1) {
    ull x; asm("mov.b64 %0, {%1, %2};" : "=l"(x) : "f"(x0), "f"(x1));
    ull y; asm("mul.rn.f32x2 %0, %1, %2;" : "=l"(y) : "l"(x), "l"(dup2(1.4426950408889634f)));
    ull tt; asm("add.rn.f32x2 %0, %1, %2;" : "=l"(tt) : "l"(y), "l"(dup2(12582912.0f)));
    ull n; asm("add.rn.f32x2 %0, %1, %2;" : "=l"(n) : "l"(tt), "l"(dup2(-12582912.0f)));
    ull f = y; fma2(f, n, dup2(-1.0f));
    ull p = dup2(9.6181291076e-3f);  fma2(p, dup2(1.3333558146e-3f), f);
    ull p2 = dup2(5.5504108664e-2f); fma2(p2, p, f);
    ull p3 = dup2(2.4022650696e-1f); fma2(p3, p2, f);
    ull p4 = dup2(6.9314718056e-1f); fma2(p4, p3, f);
    ull p5 = dup2(1.0f);             fma2(p5, p4, f);
    unsigned i0, i1;
    asm("mov.b64 {%0, %1}, %2;" : "=r"(i0), "=r"(i1) : "l"(tt));
    float s0 = __uint_as_float((i0 + 127u) << 23);
    float s1 = __uint_as_float((i1 + 127u) << 23);
    float q0, q1; unpack2(p5, q0, q1);
    r0 = q0 * s0; r1 = q1 * s1;
}

__device__ __forceinline__ void fma2s(ull& d, ull a, ull b) { fma2(d, a, b); }

__device__ __forceinline__ void split_bf16(float v, __nv_bfloat16& h, __nv_bfloat16& l) {
    h = __float2bfloat16(v);
    l = __float2bfloat16(v - __bfloat162float(h));
}

// ---------------- scratch ----------------
__device__ float g_bqk[256];
__device__ float g_bout[512];
__device__ float g_qk[(size_t)BB * 128 * NN];            // rows 64-127: k1 fp32
__device__ __nv_bfloat16 g_E2[(size_t)BB * NN * NN];
__device__ float g_Zinv[BB * NN];
__device__ float g_Gp[BB * 8 * 64 * 64];
__device__ float g_A[BB * 64 * 64];
__device__ __nv_bfloat16 g_Wh[256 * 1024];
__device__ __nv_bfloat16 g_Wl[256 * 1024];
__device__ __nv_bfloat16 g_Xh[(size_t)BB * NN * 1024];
__device__ __nv_bfloat16 g_Xl[(size_t)BB * NN * 1024];
__device__ __nv_bfloat16 g_QKTh[(size_t)BB * NN * 128];
__device__ __nv_bfloat16 g_QKTl[(size_t)BB * NN * 128];
__device__ __nv_bfloat16 g_KZh[(size_t)BB * 64 * NN];
__device__ __nv_bfloat16 g_KZl[(size_t)BB * 64 * NN];
__device__ __nv_bfloat16 g_OSh[(size_t)BB * 128 * NN];
__device__ __nv_bfloat16 g_OSl[(size_t)BB * 128 * NN];
__device__ __nv_bfloat16 g_WCh[512 * 128];
__device__ __nv_bfloat16 g_WCl[512 * 128];
__device__ __nv_bfloat16 g_CH[(size_t)BB * 128 * NN];
__device__ __nv_bfloat16 g_CL[(size_t)BB * 128 * NN];

// ---------------- fused weight folding + bf16 split ----------------
__global__ void fold_qkw(const float* __restrict__ wt, const float* __restrict__ wb,
                         const float* __restrict__ sw1, const float* __restrict__ sw2,
                         const float* __restrict__ cwq, const float* __restrict__ cwk) {
    int idx = blockIdx.x * blockDim.x + threadIdx.x;
    int j = idx >> 9, c = idx & 511;
    const float* wrow; int uoff;
    if (j < 64)       { wrow = sw1 + j * 256;        uoff = 0;   }
    else if (j < 128) { wrow = sw2 + (j - 64) * 256; uoff = 0;   }
    else if (j < 192) { wrow = cwq + (j - 128) * 256; uoff = 256; }
    else              { wrow = cwk + (j - 192) * 256; uoff = 256; }
    float at = 0.f, ab = 0.f;
    #pragma unroll 8
    for (int u = 0; u < 256; ++u) {
        float w = wrow[u];
        at = fmaf(w, wt[(uoff + u) * 512 + c], at);
        ab = fmaf(w, wb[(uoff + u) * 512 + c], ab);
    }
    __nv_bfloat16 h, l;
    split_bf16(at, h, l);
    g_Wh[j * 1024 + c] = h; g_Wl[j * 1024 + c] = l;
    split_bf16(ab, h, l);
    g_Wh[j * 1024 + 512 + c] = h; g_Wl[j * 1024 + 512 + c] = l;
}

__global__ void fold_outc(const float* __restrict__ fw, const float* __restrict__ swo,
                          const float* __restrict__ cwo) {
    int idx = blockIdx.x * blockDim.x + threadIdx.x;
    int o = idx >> 7, t = idx & 127;
    float acc = 0.f;
    if (t < 64) {
        #pragma unroll 8
        for (int u = 0; u < 256; ++u)
            acc = fmaf(fw[o * 512 + u], swo[u * 64 + t], acc);
    } else {
        int r = t - 64;
        #pragma unroll 8
        for (int u = 0; u < 256; ++u)
            acc = fmaf(fw[o * 512 + 256 + u], cwo[u * 64 + r], acc);
    }
    __nv_bfloat16 h, l; split_bf16(acc, h, l);
    g_WCh[idx] = h; g_WCl[idx] = l;
}

__global__ void fold_bias(const float* __restrict__ bt, const float* __restrict__ bb,
                          const float* __restrict__ sb1, const float* __restrict__ sb2,
                          const float* __restrict__ cbq, const float* __restrict__ cbk,
                          const float* __restrict__ fw,  const float* __restrict__ sbo,
                          const float* __restrict__ cbo, const float* __restrict__ fb,
                          const float* __restrict__ sw1, const float* __restrict__ sw2,
                          const float* __restrict__ cwq, const float* __restrict__ cwk) {
    int t = threadIdx.x;   // 512
    if (t < 256) {
        const float* wrow; int uoff; float ob;
        int j = t;
        if (j < 64)       { wrow = sw1 + j * 256;        uoff = 0;   ob = sb1[j];       }
        else if (j < 128) { wrow = sw2 + (j - 64) * 256; uoff = 0;   ob = sb2[j - 64];  }
        else if (j < 192) { wrow = cwq + (j - 128) * 256; uoff = 256; ob = cbq[j - 128]; }
        else              { wrow = cwk + (j - 192) * 256; uoff = 256; ob = cbk[j - 192]; }
        float s = ob;
        for (int u = 0; u < 256; ++u)
            s = fmaf(wrow[u], bt[uoff + u] + bb[uoff + u], s);
        g_bqk[j] = s;
    }
    float s2 = fb[t];
    for (int u = 0; u < 256; ++u) {
        s2 = fmaf(fw[t * 512 + u],       sbo[u], s2);
        s2 = fmaf(fw[t * 512 + 256 + u], cbo[u], s2);
    }
    g_bout[t] = s2;
}

__global__ void conv_x(const float* __restrict__ top, const float* __restrict__ bot) {
    __shared__ float sh[32][33];
    int b = blockIdx.z;
    int c0 = blockIdx.y * 32;
    int p0 = blockIdx.x * 32;
    const float* src = (c0 < 512) ? top : bot;
    int cs = c0 & 511;
    int tx = threadIdx.x, ty = threadIdx.y;
    #pragma unroll
    for (int k = 0; k < 4; ++k) {
        int i = ty + k * 8;
        sh[i][tx] = src[((size_t)(b * 512 + cs + i)) * NN + p0 + tx];
    }
    __syncthreads();
    #pragma unroll
    for (int k = 0; k < 4; ++k) {
        int i = ty + k * 8;
        float v = sh[tx][i];
        __nv_bfloat16 h, l; split_bf16(v, h, l);
        size_t o = ((size_t)(b * NN + p0 + i)) * 1024 + c0 + tx;
        g_Xh[o] = h; g_Xl[o] = l;
    }
}

// ---------------- qk GEMM via HMMA + cp.async double buffer (R11 config) ----------------
#define TS (128 * 72 * 2)
#define QK3_SMEM (8 * TS)
__global__ void __launch_bounds__(256) qk_tc3() {
    extern __shared__ __align__(16) char smem[];
    unsigned sb = smem_u32(smem);
    int t = threadIdx.x;
    int wid = t >> 5, lid = t & 31;
    int b = blockIdx.z;
    int j0 = blockIdx.y * 128;
    int p0 = blockIdx.x * 128;
    int wr = wid & 1;
    int wc = wid >> 1;

    const __nv_bfloat16* srcs[4] = {
        g_Wh + (size_t)j0 * 1024,
        g_Wl + (size_t)j0 * 1024,
        g_Xh + ((size_t)b * NN + p0) * 1024,
        g_Xl + ((size_t)b * NN + p0) * 1024
    };

    float c[4][4][4] = {};

    {
        #pragma unroll
        for (int tile = 0; tile < 4; ++tile) {
            unsigned base = sb + tile * TS;
            const __nv_bfloat16* s = srcs[tile];
            #pragma unroll
            for (int rep = 0; rep < 4; ++rep) {
                int u = t + rep * 256;
                int r = u >> 3, q = u & 7;
                cpa16(base + r * 144 + q * 16, s + (size_t)r * 1024 + q * 8);
            }
        }
        CP_COMMIT();
    }

    for (int ch = 0; ch < 16; ++ch) {
        if (ch + 1 < 16) {
            unsigned boff = ((ch + 1) & 1) * (4 * TS);
            int c0 = (ch + 1) * 64;
            #pragma unroll
            for (int tile = 0; tile < 4; ++tile) {
                unsigned base = sb + boff + tile * TS;
                const __nv_bfloat16* s = srcs[tile];
                #pragma unroll
                for (int rep = 0; rep < 4; ++rep) {
                    int u = t + rep * 256;
                    int r = u >> 3, q = u & 7;
                    cpa16(base + r * 144 + q * 16, s + (size_t)r * 1024 + c0 + q * 8);
                }
            }
            CP_COMMIT();
            CP_WAIT1();
        } else {
            CP_WAIT0();
        }
        __syncthreads();
        unsigned abase = sb + (ch & 1) * (4 * TS);
        unsigned aAddr = abase + (unsigned)((wr * 64 + (lid & 15)) * 144 + (lid >> 4) * 16);
        unsigned bAddr = abase + 2 * TS +
            (unsigned)((wc * 32 + ((lid >> 4) & 1) * 8 + (lid & 7)) * 144 + ((lid >> 3) & 1) * 16);
        #pragma unroll
        for (int ks = 0; ks < 4; ++ks) {
            unsigned bh[2][4], bl[2][4];
            ldsm4(bh[0], bAddr + ks * 32);
            ldsm4(bh[1], bAddr + 16 * 144 + ks * 32);
            ldsm4(bl[0], bAddr + TS + ks * 32);
            ldsm4(bl[1], bAddr + TS + 16 * 144 + ks * 32);
            #pragma unroll
            for (int mt = 0; mt < 4; ++mt) {
                unsigned ah[4], al[4];
                ldsm4(ah, aAddr + mt * 2304 + ks * 32);
                ldsm4(al, aAddr + TS + mt * 2304 + ks * 32);
                #pragma unroll
                for (int nt = 0; nt < 4; ++nt) {
                    const unsigned* bhp = &bh[nt >> 1][(nt & 1) * 2];
                    const unsigned* blp = &bl[nt >> 1][(nt & 1) * 2];
                    mma_bf16(c[mt][nt], ah, bhp);
                    mma_bf16(c[mt][nt], ah, blp);
                    mma_bf16(c[mt][nt], al, bhp);
                }
            }
        }
        __syncthreads();
    }

    int g = lid >> 2, tig = lid & 3;
    if (blockIdx.y == 0) {
        // stage bf16 hi/lo transpose in smem, write QKT; k1 rows also fp32 to g_qk
        __nv_bfloat16* Th = (__nv_bfloat16*)smem;          // [128][136]
        __nv_bfloat16* Tl = Th + 128 * 136;
        #pragma unroll
        for (int mt = 0; mt < 4; ++mt) {
            int jrow = wr * 64 + mt * 16 + g;
            float b0 = g_bqk[jrow], b1 = g_bqk[jrow + 8];
            #pragma unroll
            for (int nt = 0; nt < 4; ++nt) {
                int p = wc * 32 + nt * 8 + tig * 2;
                float v0 = c[mt][nt][0] + b0;
                float v1 = c[mt][nt][1] + b0;
                float v2 = c[mt][nt][2] + b1;
                float v3 = c[mt][nt][3] + b1;
                __nv_bfloat16 h, l;
                split_bf16(v0, h, l); Th[p * 136 + jrow] = h;       Tl[p * 136 + jrow] = l;
                split_bf16(v1, h, l); Th[(p + 1) * 136 + jrow] = h; Tl[(p + 1) * 136 + jrow] = l;
                split_bf16(v2, h, l); Th[p * 136 + jrow + 8] = h;   Tl[p * 136 + jrow + 8] = l;
                split_bf16(v3, h, l); Th[(p + 1) * 136 + jrow + 8] = h; Tl[(p + 1) * 136 + jrow + 8] = l;
                if (wr == 1) {
                    size_t r0 = ((size_t)(b * 128 + jrow)) * NN;
                    size_t r1 = r0 + (size_t)8 * NN;
                    *(float2*)&g_qk[r0 + p0 + p] = {v0, v1};
                    *(float2*)&g_qk[r1 + p0 + p] = {v2, v3};
                }
            }
        }
        __syncthreads();
        #pragma unroll
        for (int rep = 0; rep < 8; ++rep) {
            int u = t + rep * 256;
            int r = u >> 4, q = u & 15;
            size_t dst = ((size_t)(b * NN + p0 + r)) * 128 + q * 8;
            *(uint4*)(g_QKTh + dst) = *(const uint4*)&Th[r * 136 + q * 8];
            *(uint4*)(g_QKTl + dst) = *(const uint4*)&Tl[r * 136 + q * 8];
        }
    } else {
        #pragma unroll
        for (int mt = 0; mt < 4; ++mt) {
            int jl = wr * 64 + mt * 16 + g;
            float b0 = g_bqk[128 + jl], b1 = g_bqk[128 + jl + 8];
            size_t r0 = ((size_t)(b * 128 + jl)) * NN;
            size_t r1 = r0 + (size_t)8 * NN;
            #pragma unroll
            for (int nt = 0; nt < 4; ++nt) {
                int pc = p0 + wc * 32 + nt * 8 + tig * 2;
                __nv_bfloat16 h0, l0, h1, l1;
                split_bf16(c[mt][nt][0] + b0, h0, l0);
                split_bf16(c[mt][nt][1] + b0, h1, l1);
                *(__nv_bfloat162*)&g_CH[r0 + pc] = {h0, h1};
                *(__nv_bfloat162*)&g_CL[r0 + pc] = {l0, l1};
                split_bf16(c[mt][nt][2] + b1, h0, l0);
                split_bf16(c[mt][nt][3] + b1, h1, l1);
                *(__nv_bfloat162*)&g_CH[r1 + pc] = {h0, h1};
                *(__nv_bfloat162*)&g_CL[r1 + pc] = {l0, l1};
            }
        }
    }
}

// ---------------- spatial pass A (HMMA + packed exp + fused Kz epilogue) ----------------
#define PAT 18432
#define PA_SMEM (6 * PAT + 2048 + 512)
__global__ void __launch_bounds__(256, 2) passA_tc() {
    extern __shared__ __align__(16) char smem[];
    unsigned sb = smem_u32(smem);
    int t = threadIdx.x;
    int wid = t >> 5, lid = t & 31;
    int b = blockIdx.y;
    int n0 = blockIdx.x * 128;
    int wr = wid & 1;
    int wc = wid >> 1;
    int g = lid >> 2, tig = lid & 3;

    #pragma unroll
    for (int rep = 0; rep < 4; ++rep) {
        int u = t + rep * 256;
        int r = u >> 3, q = u & 7;
        size_t src = ((size_t)b * NN + n0 + r) * 128 + q * 8;
        cpa16(sb + r * 144 + q * 16, g_QKTh + src);
        cpa16(sb + PAT + r * 144 + q * 16, g_QKTl + src);
    }
    #pragma unroll
    for (int rep = 0; rep < 4; ++rep) {
        int u = t + rep * 256;
        int r = u >> 3, q = u & 7;
        size_t src = ((size_t)b * NN + r) * 128 + 64 + q * 8;
        cpa16(sb + 2 * PAT + r * 144 + q * 16, g_QKTh + src);
        cpa16(sb + 3 * PAT + r * 144 + q * 16, g_QKTl + src);
    }
    CP_COMMIT();

    unsigned aAddrH = sb + (unsigned)((wr * 64 + (lid & 15)) * 144 + (lid >> 4) * 16);

    float zacc[8] = {};
    size_t ebase = ((size_t)b) << 24;

    for (int ch = 0; ch < 32; ++ch) {
        int m0 = ch * 128;
        if (ch + 1 < 32) {
            unsigned kb = 2 * PAT + ((ch + 1) & 1) * 2 * PAT;
            int m1 = (ch + 1) * 128;
            #pragma unroll
            for (int rep = 0; rep < 4; ++rep) {
                int u = t + rep * 256;
                int r = u >> 3, q = u & 7;
                size_t src = ((size_t)b * NN + m1 + r) * 128 + 64 + q * 8;
                cpa16(sb + kb + r * 144 + q * 16, g_QKTh + src);
                cpa16(sb + kb + PAT + r * 144 + q * 16, g_QKTl + src);
            }
            CP_COMMIT();
            CP_WAIT1();
        } else {
            CP_WAIT0();
        }
        __syncthreads();
        unsigned kb = 2 * PAT + (ch & 1) * 2 * PAT;
        unsigned bAddrH = sb + kb +
            (unsigned)((wc * 32 + ((lid >> 4) & 1) * 8 + (lid & 7)) * 144 + ((lid >> 3) & 1) * 16);
        float c[4][4][4] = {};
        #pragma unroll
        for (int ks = 0; ks < 4; ++ks) {
            unsigned bh[2][4], bl[2][4];
            ldsm4(bh[0], bAddrH + ks * 32);
            ldsm4(bh[1], bAddrH + 16 * 144 + ks * 32);
            ldsm4(bl[0], bAddrH + PAT + ks * 32);
            ldsm4(bl[1], bAddrH + PAT + 16 * 144 + ks * 32);
            #pragma unroll
            for (int mt = 0; mt < 4; ++mt) {
                unsigned ah[4], al[4];
                ldsm4(ah, aAddrH + mt * 2304 + ks * 32);
                ldsm4(al, aAddrH + PAT + mt * 2304 + ks * 32);
                #pragma unroll
                for (int nt = 0; nt < 4; ++nt) {
                    const unsigned* bhp = &bh[nt >> 1][(nt & 1) * 2];
                    const unsigned* blp = &bl[nt >> 1][(nt & 1) * 2];
                    mma_bf16(c[mt][nt], ah, bhp);
                    mma_bf16(c[mt][nt], ah, blp);
                    mma_bf16(c[mt][nt], al, bhp);
                }
            }
        }
        #pragma unroll
        for (int mt = 0; mt < 4; ++mt) {
            int n = n0 + wr * 64 + mt * 16 + g;
            #pragma unroll
            for (int nt = 0; nt < 4; ++nt) {
                int m = m0 + wc * 32 + nt * 8 + tig * 2;
                float e0, e1, e2, e3;
                fexp2x(c[mt][nt][0], c[mt][nt][1], e0, e1);
                fexp2x(c[mt][nt][2], c[mt][nt][3], e2, e3);
                __nv_bfloat162 v0 = {__float2bfloat16(e0), __float2bfloat16(e1)};
                __nv_bfloat162 v1 = {__float2bfloat16(e2), __float2bfloat16(e3)};
                *(__nv_bfloat162*)&g_E2[ebase + (size_t)n * NN + m] = v0;
                *(__nv_bfloat162*)&g_E2[ebase + (size_t)(n + 8) * NN + m] = v1;
                zacc[mt * 2] += e0 + e1;
                zacc[mt * 2 + 1] += e2 + e3;
            }
        }
        __syncthreads();
    }

    float* zp = (float*)(smem + 6 * PAT);
    float* zsm = (float*)(smem + 6 * PAT + 2048);
    #pragma unroll
    for (int s = 0; s < 8; ++s) {
        float v = zacc[s];
        v += __shfl_xor_sync(0xFFFFFFFF, v, 1);
        v += __shfl_xor_sync(0xFFFFFFFF, v, 2);
        if (tig == 0)
            zp[wc * 128 + wr * 64 + (s >> 1) * 16 + (s & 1) * 8 + g] = v;
    }
    __syncthreads();
    if (t < 128) {
        float s = zp[t] + zp[128 + t] + zp[256 + t] + zp[384 + t];
        float zi = 1.0f / s;
        g_Zinv[b * NN + n0 + t] = zi;
        zsm[t] = zi;
    }
    __syncthreads();

    #pragma unroll
    for (int rep = 0; rep < 8; ++rep) {
        int idx = t + rep * 256;
        int r = idx >> 5;
        int nq = (idx & 31) * 4;
        float4 k4 = *(const float4*)&g_qk[((size_t)(b * 128 + 64 + r)) * NN + n0 + nq];
        float v0 = k4.x * zsm[nq];
        float v1 = k4.y * zsm[nq + 1];
        float v2 = k4.z * zsm[nq + 2];
        float v3 = k4.w * zsm[nq + 3];
        __nv_bfloat16 h0, l0, h1, l1;
        size_t o = ((size_t)b * 64 + r) * NN + n0 + nq;
        split_bf16(v0, h0, l0); split_bf16(v1, h1, l1);
        *(__nv_bfloat162*)&g_KZh[o] = {h0, h1};
        *(__nv_bfloat162*)&g_KZl[o] = {l0, l1};
        split_bf16(v2, h0, l0); split_bf16(v3, h1, l1);
        *(__nv_bfloat162*)&g_KZh[o + 2] = {h0, h1};
        *(__nv_bfloat162*)&g_KZl[o + 2] = {l0, l1};
    }
}

// ---------------- spatial pass B ----------------
#define PBS 35840
#define PB_SMEM (2 * PBS)
__global__ void __launch_bounds__(256, 2) passB_tc() {
    extern __shared__ __align__(16) char smem[];
    unsigned sb = smem_u32(smem);
    int t = threadIdx.x;
    int wid = t >> 5, lid = t & 31;
    int b = blockIdx.y;
    int m0 = blockIdx.x * 128;
    int g = lid >> 2, tig = lid & 3;

    float c[4][2][4] = {};
    size_t ebase = ((size_t)b) << 24;

    {
        #pragma unroll
        for (int rep = 0; rep < 2; ++rep) {
            int u = t + rep * 256;
            int r = u >> 3, q = u & 7;
            size_t src = ((size_t)b * 64 + r) * NN + q * 8;
            cpa16(sb + r * 144 + q * 16, g_KZh + src);
            cpa16(sb + 9216 + r * 144 + q * 16, g_KZl + src);
        }
        #pragma unroll
        for (int rep = 0; rep < 4; ++rep) {
            int u = t + rep * 256;
            int r = u >> 4, q = u & 15;
            cpa16(sb + 18432 + r * 272 + q * 16, g_E2 + ebase + (size_t)r * NN + m0 + q * 8);
        }
        CP_COMMIT();
    }

    for (int ch = 0; ch < 64; ++ch) {
        if (ch + 1 < 64) {
            unsigned boff = ((ch + 1) & 1) * PBS;
            int n1 = (ch + 1) * 64;
            #pragma unroll
            for (int rep = 0; rep < 2; ++rep) {
                int u = t + rep * 256;
                int r = u >> 3, q = u & 7;
                size_t src = ((size_t)b * 64 + r) * NN + n1 + q * 8;
                cpa16(sb + boff + r * 144 + q * 16, g_KZh + src);
                cpa16(sb + boff + 9216 + r * 144 + q * 16, g_KZl + src);
            }
            #pragma unroll
            for (int rep = 0; rep < 4; ++rep) {
                int u = t + rep * 256;
                int r = u >> 4, q = u & 15;
                cpa16(sb + boff + 18432 + r * 272 + q * 16,
                      g_E2 + ebase + (size_t)(n1 + r) * NN + m0 + q * 8);
            }
            CP_COMMIT();
            CP_WAIT1();
        } else {
            CP_WAIT0();
        }
        __syncthreads();
        unsigned boff = (ch & 1) * PBS;
        unsigned aAddrH = sb + boff + (unsigned)(((lid & 15)) * 144 + (lid >> 4) * 16);
        unsigned eAddr = sb + boff + 18432 +
            (unsigned)(((lid & 7) + ((lid >> 3) & 1) * 8) * 272 + (wid * 16 + (lid >> 4) * 8) * 2);
        #pragma unroll
        for (int ks = 0; ks < 4; ++ks) {
            unsigned eb[4];
            ldsm4t(eb, eAddr + ks * 16 * 272);
            #pragma unroll
            for (int mt = 0; mt < 4; ++mt) {
                unsigned ah[4], al[4];
                ldsm4(ah, aAddrH + mt * 2304 + ks * 32);
                ldsm4(al, aAddrH + 9216 + mt * 2304 + ks * 32);
                #pragma unroll
                for (int nt = 0; nt < 2; ++nt) {
                    mma_bf16(c[mt][nt], ah, &eb[nt * 2]);
                    mma_bf16(c[mt][nt], al, &eb[nt * 2]);
                }
            }
        }
        __syncthreads();
    }

    #pragma unroll
    for (int mt = 0; mt < 4; ++mt) {
        int r = mt * 16 + g;
        size_t r0 = ((size_t)(b * 128 + r)) * NN;
        size_t r1 = r0 + (size_t)8 * NN;
        #pragma unroll
        for (int nt = 0; nt < 2; ++nt) {
            int m = m0 + wid * 16 + nt * 8 + tig * 2;
            __nv_bfloat16 h0, l0, h1, l1;
            split_bf16(c[mt][nt][0], h0, l0);
            split_bf16(c[mt][nt][1], h1, l1);
            *(__nv_bfloat162*)&g_OSh[r0 + m] = {h0, h1};
            *(__nv_bfloat162*)&g_OSl[r0 + m] = {l0, l1};
            split_bf16(c[mt][nt][2], h0, l0);
            split_bf16(c[mt][nt][3], h1, l1);
            *(__nv_bfloat162*)&g_OSh[r1 + m] = {h0, h1};
            *(__nv_bfloat162*)&g_OSl[r1 + m] = {l0, l1};
        }
    }
}

// ---------------- channel Gram via HMMA ----------------
__global__ void __launch_bounds__(128) chan_gram_tc() {
    __shared__ __align__(16) char csm[4 * 9216];
    unsigned sb = smem_u32(csm);
    int t = threadIdx.x;
    int wid = t >> 5, lid = t & 31;
    int b = blockIdx.y;
    int chunk = blockIdx.x;
    int wr = wid & 1, wc = wid >> 1;
    int g = lid >> 2, tig = lid & 3;

    unsigned aAddr = sb + (unsigned)((wr * 32 + (lid & 15)) * 144 + (lid >> 4) * 16);
    unsigned bAddr = sb + 2 * 9216 +
        (unsigned)((wc * 32 + ((lid >> 4) & 1) * 8 + (lid & 7)) * 144 + ((lid >> 3) & 1) * 16);

    float c[2][4][4] = {};

    for (int sub = 0; sub < 8; ++sub) {
        int n0 = chunk * 512 + sub * 64;
        __syncthreads();
        #pragma unroll
        for (int rep = 0; rep < 4; ++rep) {
            int u = t + rep * 128;
            int r = u >> 3, q = u & 7;
            size_t sq = ((size_t)(b * 128 + r)) * NN + n0 + q * 8;
            size_t sk = ((size_t)(b * 128 + 64 + r)) * NN + n0 + q * 8;
            *(uint4*)(csm + r * 144 + q * 16) = *(const uint4*)(g_CH + sq);
            *(uint4*)(csm + 9216 + r * 144 + q * 16) = *(const uint4*)(g_CL + sq);
            *(uint4*)(csm + 2 * 9216 + r * 144 + q * 16) = *(const uint4*)(g_CH + sk);
            *(uint4*)(csm + 3 * 9216 + r * 144 + q * 16) = *(const uint4*)(g_CL + sk);
        }
        __syncthreads();
        #pragma unroll
        for (int ks = 0; ks < 4; ++ks) {
            unsigned bh[2][4], bl[2][4];
            ldsm4(bh[0], bAddr + ks * 32);
            ldsm4(bh[1], bAddr + 16 * 144 + ks * 32);
            ldsm4(bl[0], bAddr + 9216 + ks * 32);
            ldsm4(bl[1], bAddr + 9216 + 16 * 144 + ks * 32);
            #pragma unroll
            for (int mt = 0; mt < 2; ++mt) {
                unsigned ah[4], al[4];
                ldsm4(ah, aAddr + mt * 2304 + ks * 32);
                ldsm4(al, aAddr + 9216 + mt * 2304 + ks * 32);
                #pragma unroll
                for (int nt = 0; nt < 4; ++nt) {
                    const unsigned* bhp = &bh[nt >> 1][(nt & 1) * 2];
                    const unsigned* blp = &bl[nt >> 1][(nt & 1) * 2];
                    mma_bf16(c[mt][nt], ah, bhp);
                    mma_bf16(c[mt][nt], ah, blp);
                    mma_bf16(c[mt][nt], al, bhp);
                }
            }
        }
    }

    float* gp = &g_Gp[(b * 8 + chunk) * 4096];
    #pragma unroll
    for (int mt = 0; mt < 2; ++mt) {
        int r = wr * 32 + mt * 16 + g;
        #pragma unroll
        for (int nt = 0; nt < 4; ++nt) {
            int s = wc * 32 + nt * 8 + tig * 2;
            *(float2*)&gp[r * 64 + s] = {c[mt][nt][0], c[mt][nt][1]};
            *(float2*)&gp[(r + 8) * 64 + s] = {c[mt][nt][2], c[mt][nt][3]};
        }
    }
}

__global__ void chan_softmax() {
    int r = blockIdx.x;
    int b = blockIdx.y;
    int s = threadIdx.x;
    __shared__ float red[64];
    float v = 0.f;
    #pragma unroll
    for (int ch = 0; ch < 8; ++ch)
        v += g_Gp[(b * 8 + ch) * 4096 + r * 64 + s];
    red[s] = v;
    __syncthreads();
    for (int off = 32; off >= 1; off >>= 1) {
        if (s < off) red[s] = fmaxf(red[s], red[s + off]);
        __syncthreads();
    }
    float mx = red[0];
    __syncthreads();
    float e = __expf(v - mx);
    red[s] = e;
    __syncthreads();
    for (int off = 32; off >= 1; off >>= 1) {
        if (s < off) red[s] += red[s + off];
        __syncthreads();
    }
    g_A[b * 4096 + r * 64 + s] = e / red[0];
}

__global__ void __launch_bounds__(256) chan_out() {
    int b = blockIdx.y;
    int p = blockIdx.x * 256 + threadIdx.x;
    __shared__ __align__(16) float As[64][64];
    #pragma unroll
    for (int k = 0; k < 16; ++k)
        (&As[0][0])[threadIdx.x + k * 256] = g_A[b * 4096 + threadIdx.x + k * 256];
    __syncthreads();
    float kreg[64];
    #pragma unroll
    for (int s = 0; s < 64; ++s) {
        size_t o = ((size_t)(b * 128 + 64 + s)) * NN + p;
        kreg[s] = __bfloat162float(g_CH[o]) + __bfloat162float(g_CL[o]);
    }
    ull kp2[32];
    #pragma unroll
    for (int s = 0; s < 32; ++s) {
        ull r; asm("mov.b64 %0, {%1, %2};" : "=l"(r) : "f"(kreg[2 * s]), "f"(kreg[2 * s + 1]));
        kp2[s] = r;
    }
    #pragma unroll 2
    for (int r = 0; r < 64; ++r) {
        ull acc = 0;
        const ull* arow = (const ull*)&As[r][0];
        #pragma unroll
        for (int s = 0; s < 32; ++s)
            fma2s(acc, arow[s], kp2[s]);
        float lo, hi;
        unpack2(acc, lo, hi);
        float v = lo + hi;
        __nv_bfloat16 h, l; split_bf16(v, h, l);
        size_t o = ((size_t)(b * 128 + 64 + r)) * NN + p;
        g_OSh[o] = h; g_OSl[o] = l;
    }
}

// ---------------- final GEMM via HMMA (3-pass) ----------------
#define FT_SMEM 139264
__global__ void __launch_bounds__(256) final_tc(float* __restrict__ out) {
    extern __shared__ __align__(16) char smem[];
    unsigned sb = smem_u32(smem);
    int t = threadIdx.x;
    int wid = t >> 5, lid = t & 31;
    int b = blockIdx.z;
    int o0 = blockIdx.y * 128;
    int p0 = blockIdx.x * 128;
    int wr = wid & 1, wc = wid >> 1;
    int g = lid >> 2, tig = lid & 3;

    #pragma unroll
    for (int rep = 0; rep < 8; ++rep) {
        int u = t + rep * 256;
        int r = u >> 4, q = u & 15;
        *(uint4*)(smem + r * 272 + q * 16) = *(const uint4*)(g_WCh + (size_t)(o0 + r) * 128 + q * 8);
        *(uint4*)(smem + 34816 + r * 272 + q * 16) = *(const uint4*)(g_WCl + (size_t)(o0 + r) * 128 + q * 8);
        size_t bs = ((size_t)(b * 128 + r)) * NN + p0 + q * 8;
        *(uint4*)(smem + 69632 + r * 272 + q * 16) = *(const uint4*)(g_OSh + bs);
        *(uint4*)(smem + 104448 + r * 272 + q * 16) = *(const uint4*)(g_OSl + bs);
    }
    __syncthreads();

    unsigned aAddr = sb + (unsigned)((wr * 64 + (lid & 15)) * 272 + (lid >> 4) * 16);
    unsigned eAddr = sb + 69632 +
        (unsigned)(((lid & 7) + ((lid >> 3) & 1) * 8) * 272 + (wc * 32 + (lid >> 4) * 8) * 2);

    float c[4][4][4] = {};
    #pragma unroll
    for (int ks = 0; ks < 8; ++ks) {
        unsigned bh[2][4], bl[2][4];
        ldsm4t(bh[0], eAddr + ks * 16 * 272);
        ldsm4t(bh[1], eAddr + ks * 16 * 272 + 32);
        ldsm4t(bl[0], eAddr + 34816 + ks * 16 * 272);
        ldsm4t(bl[1], eAddr + 34816 + ks * 16 * 272 + 32);
        #pragma unroll
        for (int mt = 0; mt < 4; ++mt) {
            unsigned ah[4], al[4];
            ldsm4(ah, aAddr + mt * 16 * 272 + ks * 32);
            ldsm4(al, aAddr + 34816 + mt * 16 * 272 + ks * 32);
            #pragma unroll
            for (int nt = 0; nt < 4; ++nt) {
                const unsigned* bhp = &bh[nt >> 1][(nt & 1) * 2];
                const unsigned* blp = &bl[nt >> 1][(nt & 1) * 2];
                mma_bf16(c[mt][nt], ah, bhp);
                mma_bf16(c[mt][nt], ah, blp);
                mma_bf16(c[mt][nt], al, bhp);
            }
        }
    }

    #pragma unroll
    for (int mt = 0; mt < 4; ++mt) {
        int o = o0 + wr * 64 + mt * 16 + g;
        float b0 = g_bout[o], b1 = g_bout[o + 8];
        size_t r0 = ((size_t)(b * 512 + o)) * NN;
        size_t r1 = r0 + (size_t)8 * NN;
        #pragma unroll
        for (int nt = 0; nt < 4; ++nt) {
            int pc = p0 + wc * 32 + nt * 8 + tig * 2;
            float2 v0 = {c[mt][nt][0] + b0, c[mt][nt][1] + b0};
            float2 v1 = {c[mt][nt][2] + b1, c[mt][nt][3] + b1};
            *(float2*)&out[r0 + pc] = v0;
            *(float2*)&out[r1 + pc] = v1;
        }
    }
}

// ---------------- launch ----------------
extern "C" void kernel_launch(void* const* d_in, const int* in_sizes, int n_in,
                              void* d_out, int out_size) {
    const float* top  = (const float*)d_in[0];
    const float* bot  = (const float*)d_in[1];
    const float* wt   = (const float*)d_in[2];
    const float* bt   = (const float*)d_in[3];
    const float* wb   = (const float*)d_in[4];
    const float* bb   = (const float*)d_in[5];
    const float* s_w1 = (const float*)d_in[6];
    const float* s_b1 = (const float*)d_in[7];
    const float* s_w2 = (const float*)d_in[8];
    const float* s_b2 = (const float*)d_in[9];
    const float* s_wo = (const float*)d_in[10];
    const float* s_bo = (const float*)d_in[11];
    const float* c_wq = (const float*)d_in[12];
    const float* c_bq = (const float*)d_in[13];
    const float* c_wk = (const float*)d_in[14];
    const float* c_bk = (const float*)d_in[15];
    const float* c_wo = (const float*)d_in[16];
    const float* c_bo = (const float*)d_in[17];
    const float* f_w  = (const float*)d_in[18];
    const float* f_b  = (const float*)d_in[19];
    float* out = (float*)d_out;

    static cudaStream_t s2 = 0;
    static cudaEvent_t evStart = 0, evPre = 0, evQk = 0, evChan = 0;
    if (!s2) {
        cudaStreamCreateWithFlags(&s2, cudaStreamNonBlocking);
        cudaEventCreateWithFlags(&evStart, cudaEventDisableTiming);
        cudaEventCreateWithFlags(&evPre, cudaEventDisableTiming);
        cudaEventCreateWithFlags(&evQk, cudaEventDisableTiming);
        cudaEventCreateWithFlags(&evChan, cudaEventDisableTiming);
        cudaFuncSetAttribute(qk_tc3, cudaFuncAttributeMaxDynamicSharedMemorySize, QK3_SMEM);
        cudaFuncSetAttribute(passA_tc, cudaFuncAttributeMaxDynamicSharedMemorySize, PA_SMEM);
        cudaFuncSetAttribute(passB_tc, cudaFuncAttributeMaxDynamicSharedMemorySize, PB_SMEM);
        cudaFuncSetAttribute(final_tc, cudaFuncAttributeMaxDynamicSharedMemorySize, FT_SMEM);
    }

    cudaEventRecord(evStart, 0);
    cudaStreamWaitEvent(s2, evStart, 0);

    fold_qkw<<<512, 256>>>(wt, wb, s_w1, s_w2, c_wq, c_wk);
    fold_bias<<<1, 512>>>(bt, bb, s_b1, s_b2, c_bq, c_bk, f_w, s_bo, c_bo, f_b,
                          s_w1, s_w2, c_wq, c_wk);
    conv_x<<<dim3(128, 32, 8), dim3(32, 8), 0, s2>>>(top, bot);
    cudaEventRecord(evPre, s2);
    cudaStreamWaitEvent(0, evPre, 0);

    qk_tc3<<<dim3(32, 2, 8), 256, QK3_SMEM>>>();
    cudaEventRecord(evQk, 0);

    cudaStreamWaitEvent(s2, evQk, 0);
    fold_outc<<<256, 256, 0, s2>>>(f_w, s_wo, c_wo);
    chan_gram_tc<<<dim3(8, 8), 128, 0, s2>>>();
    chan_softmax<<<dim3(64, 8), 64, 0, s2>>>();
    chan_out<<<dim3(16, 8), 256, 0, s2>>>();
    cudaEventRecord(evChan, s2);

    passA_tc<<<dim3(32, 8), 256, PA_SMEM>>>();
    passB_tc<<<dim3(32, 8), 256, PB_SMEM>>>();

    cudaStreamWaitEvent(0, evChan, 0);
    final_tc<<<dim3(32, 4, 8), 256, FT_SMEM>>>(out);
}

// round 17
// speedup vs baseline: 1.5419x; 1.0330x over previous
#include <cuda_runtime.h>
#include <cuda_bf16.h>
#include <stdint.h>
#include <math.h>

#define BB 8
#define NN 4096

typedef unsigned long long ull;

__device__ __forceinline__ ull dup2(float x) {
    ull r; asm("mov.b64 %0, {%1, %1};" : "=l"(r) : "f"(x)); return r;
}
__device__ __forceinline__ void unpack2(ull v, float& x, float& y) {
    asm("mov.b64 {%0, %1}, %2;" : "=f"(x), "=f"(y) : "l"(v));
}
__device__ __forceinline__ void fma2(ull& d, ull a, ull b) {
    asm("fma.rn.f32x2 %0, %1, %2, %0;" : "+l"(d) : "l"(a), "l"(b));
}

__device__ __forceinline__ unsigned smem_u32(const void* p) {
    unsigned a;
    asm("{ .reg .u64 t; cvta.to.shared.u64 t, %1; cvt.u32.u64 %0, t; }" : "=r"(a) : "l"(p));
    return a;
}
__device__ __forceinline__ void ldsm4(unsigned* r, unsigned addr) {
    asm volatile("ldmatrix.sync.aligned.m8n8.x4.shared.b16 {%0,%1,%2,%3}, [%4];"
        : "=r"(r[0]), "=r"(r[1]), "=r"(r[2]), "=r"(r[3]) : "r"(addr));
}
__device__ __forceinline__ void ldsm4t(unsigned* r, unsigned addr) {
    asm volatile("ldmatrix.sync.aligned.m8n8.x4.trans.shared.b16 {%0,%1,%2,%3}, [%4];"
        : "=r"(r[0]), "=r"(r[1]), "=r"(r[2]), "=r"(r[3]) : "r"(addr));
}
__device__ __forceinline__ void mma_bf16(float* c, const unsigned* a, const unsigned* b) {
    asm volatile("mma.sync.aligned.m16n8k16.row.col.f32.bf16.bf16.f32 "
        "{%0,%1,%2,%3}, {%4,%5,%6,%7}, {%8,%9}, {%0,%1,%2,%3};"
        : "+f"(c[0]), "+f"(c[1]), "+f"(c[2]), "+f"(c[3])
        : "r"(a[0]), "r"(a[1]), "r"(a[2]), "r"(a[3]), "r"(b[0]), "r"(b[1]));
}
__device__ __forceinline__ void cpa16(unsigned s, const void* g) {
    asm volatile("cp.async.ca.shared.global [%0], [%1], 16;" :: "r"(s), "l"(g));
}
#define CP_COMMIT() asm volatile("cp.async.commit_group;" ::: "memory")
#define CP_WAIT0() asm volatile("cp.async.wait_group 0;" ::: "memory")
#define CP_WAIT1() asm volatile("cp.async.wait_group 1;" ::: "memory")
#define CP_WAIT2() asm volatile("cp.async.wait_group 2;" ::: "memory")

// packed f32x2 exp
__device__ __forceinline__ void fexp2x(float x0, float x1, float& r0, float& r1) {
    ull x; asm("mov.b64 %0, {%1, %2};" : "=l"(x) : "f"(x0), "f"(x1));
    ull y; asm("mul.rn.f32x2 %0, %1, %2;" : "=l"(y) : "l"(x), "l"(dup2(1.4426950408889634f)));
    ull tt; asm("add.rn.f32x2 %0, %1, %2;" : "=l"(tt) : "l"(y), "l"(dup2(12582912.0f)));
    ull n; asm("add.rn.f32x2 %0, %1, %2;" : "=l"(n) : "l"(tt), "l"(dup2(-12582912.0f)));
    ull f = y; fma2(f, n, dup2(-1.0f));
    ull p = dup2(9.6181291076e-3f);  fma2(p, dup2(1.3333558146e-3f), f);
    ull p2 = dup2(5.5504108664e-2f); fma2(p2, p, f);
    ull p3 = dup2(2.4022650696e-1f); fma2(p3, p2, f);
    ull p4 = dup2(6.9314718056e-1f); fma2(p4, p3, f);
    ull p5 = dup2(1.0f);             fma2(p5, p4, f);
    unsigned i0, i1;
    asm("mov.b64 {%0, %1}, %2;" : "=r"(i0), "=r"(i1) : "l"(tt));
    float s0 = __uint_as_float((i0 + 127u) << 23);
    float s1 = __uint_as_float((i1 + 127u) << 23);
    float q0, q1; unpack2(p5, q0, q1);
    r0 = q0 * s0; r1 = q1 * s1;
}

__device__ __forceinline__ void fma2s(ull& d, ull a, ull b) { fma2(d, a, b); }

__device__ __forceinline__ void split_bf16(float v, __nv_bfloat16& h, __nv_bfloat16& l) {
    h = __float2bfloat16(v);
    l = __float2bfloat16(v - __bfloat162float(h));
}

// ---------------- scratch ----------------
__device__ float g_bqk[256];
__device__ float g_bout[512];
__device__ float g_qk[(size_t)BB * 128 * NN];            // rows 64-127: k1 fp32
__device__ __nv_bfloat16 g_E2[(size_t)BB * NN * NN];
__device__ float g_Zinv[BB * NN];
__device__ float g_Gp[BB * 8 * 64 * 64];
__device__ float g_A[BB * 64 * 64];
__device__ __nv_bfloat16 g_Wh[256 * 1024];
__device__ __nv_bfloat16 g_Wl[256 * 1024];
__device__ __nv_bfloat16 g_Xh[(size_t)BB * NN * 1024];
__device__ __nv_bfloat16 g_Xl[(size_t)BB * NN * 1024];
__device__ __nv_bfloat16 g_QKTh[(size_t)BB * NN * 128];
__device__ __nv_bfloat16 g_QKTl[(size_t)BB * NN * 128];
__device__ __nv_bfloat16 g_KZh[(size_t)BB * 64 * NN];
__device__ __nv_bfloat16 g_KZl[(size_t)BB * 64 * NN];
__device__ __nv_bfloat16 g_OSh[(size_t)BB * 128 * NN];
__device__ __nv_bfloat16 g_OSl[(size_t)BB * 128 * NN];
__device__ __nv_bfloat16 g_WCh[512 * 128];
__device__ __nv_bfloat16 g_WCl[512 * 128];
__device__ __nv_bfloat16 g_CH[(size_t)BB * 128 * NN];
__device__ __nv_bfloat16 g_CL[(size_t)BB * 128 * NN];

// ---------------- fused weight folding + bf16 split ----------------
__global__ void fold_qkw(const float* __restrict__ wt, const float* __restrict__ wb,
                         const float* __restrict__ sw1, const float* __restrict__ sw2,
                         const float* __restrict__ cwq, const float* __restrict__ cwk) {
    int idx = blockIdx.x * blockDim.x + threadIdx.x;
    int j = idx >> 9, c = idx & 511;
    const float* wrow; int uoff;
    if (j < 64)       { wrow = sw1 + j * 256;        uoff = 0;   }
    else if (j < 128) { wrow = sw2 + (j - 64) * 256; uoff = 0;   }
    else if (j < 192) { wrow = cwq + (j - 128) * 256; uoff = 256; }
    else              { wrow = cwk + (j - 192) * 256; uoff = 256; }
    float at = 0.f, ab = 0.f;
    #pragma unroll 8
    for (int u = 0; u < 256; ++u) {
        float w = wrow[u];
        at = fmaf(w, wt[(uoff + u) * 512 + c], at);
        ab = fmaf(w, wb[(uoff + u) * 512 + c], ab);
    }
    __nv_bfloat16 h, l;
    split_bf16(at, h, l);
    g_Wh[j * 1024 + c] = h; g_Wl[j * 1024 + c] = l;
    split_bf16(ab, h, l);
    g_Wh[j * 1024 + 512 + c] = h; g_Wl[j * 1024 + 512 + c] = l;
}

__global__ void fold_outc(const float* __restrict__ fw, const float* __restrict__ swo,
                          const float* __restrict__ cwo) {
    int idx = blockIdx.x * blockDim.x + threadIdx.x;
    int o = idx >> 7, t = idx & 127;
    float acc = 0.f;
    if (t < 64) {
        #pragma unroll 8
        for (int u = 0; u < 256; ++u)
            acc = fmaf(fw[o * 512 + u], swo[u * 64 + t], acc);
    } else {
        int r = t - 64;
        #pragma unroll 8
        for (int u = 0; u < 256; ++u)
            acc = fmaf(fw[o * 512 + 256 + u], cwo[u * 64 + r], acc);
    }
    __nv_bfloat16 h, l; split_bf16(acc, h, l);
    g_WCh[idx] = h; g_WCl[idx] = l;
}

__global__ void fold_bias(const float* __restrict__ bt, const float* __restrict__ bb,
                          const float* __restrict__ sb1, const float* __restrict__ sb2,
                          const float* __restrict__ cbq, const float* __restrict__ cbk,
                          const float* __restrict__ fw,  const float* __restrict__ sbo,
                          const float* __restrict__ cbo, const float* __restrict__ fb,
                          const float* __restrict__ sw1, const float* __restrict__ sw2,
                          const float* __restrict__ cwq, const float* __restrict__ cwk) {
    int t = threadIdx.x;   // 512
    if (t < 256) {
        const float* wrow; int uoff; float ob;
        int j = t;
        if (j < 64)       { wrow = sw1 + j * 256;        uoff = 0;   ob = sb1[j];       }
        else if (j < 128) { wrow = sw2 + (j - 64) * 256; uoff = 0;   ob = sb2[j - 64];  }
        else if (j < 192) { wrow = cwq + (j - 128) * 256; uoff = 256; ob = cbq[j - 128]; }
        else              { wrow = cwk + (j - 192) * 256; uoff = 256; ob = cbk[j - 192]; }
        float s = ob;
        for (int u = 0; u < 256; ++u)
            s = fmaf(wrow[u], bt[uoff + u] + bb[uoff + u], s);
        g_bqk[j] = s;
    }
    float s2 = fb[t];
    for (int u = 0; u < 256; ++u) {
        s2 = fmaf(fw[t * 512 + u],       sbo[u], s2);
        s2 = fmaf(fw[t * 512 + 256 + u], cbo[u], s2);
    }
    g_bout[t] = s2;
}

__global__ void conv_x(const float* __restrict__ top, const float* __restrict__ bot) {
    __shared__ float sh[32][33];
    int b = blockIdx.z;
    int c0 = blockIdx.y * 32;
    int p0 = blockIdx.x * 32;
    const float* src = (c0 < 512) ? top : bot;
    int cs = c0 & 511;
    int tx = threadIdx.x, ty = threadIdx.y;
    #pragma unroll
    for (int k = 0; k < 4; ++k) {
        int i = ty + k * 8;
        sh[i][tx] = src[((size_t)(b * 512 + cs + i)) * NN + p0 + tx];
    }
    __syncthreads();
    #pragma unroll
    for (int k = 0; k < 4; ++k) {
        int i = ty + k * 8;
        float v = sh[tx][i];
        __nv_bfloat16 h, l; split_bf16(v, h, l);
        size_t o = ((size_t)(b * NN + p0 + i)) * 1024 + c0 + tx;
        g_Xh[o] = h; g_Xl[o] = l;
    }
}

// ---------------- qk GEMM via HMMA + cp.async 3-stage pipeline ----------------
#define TS (128 * 72 * 2)
#define QK3_SMEM (12 * TS)       // 221184 B, 3 stages
__global__ void __launch_bounds__(256) qk_tc3() {
    extern __shared__ __align__(16) char smem[];
    unsigned sb = smem_u32(smem);
    int t = threadIdx.x;
    int wid = t >> 5, lid = t & 31;
    int b = blockIdx.z;
    int j0 = blockIdx.y * 128;
    int p0 = blockIdx.x * 128;
    int wr = wid & 1;
    int wc = wid >> 1;

    const __nv_bfloat16* srcs[4] = {
        g_Wh + (size_t)j0 * 1024,
        g_Wl + (size_t)j0 * 1024,
        g_Xh + ((size_t)b * NN + p0) * 1024,
        g_Xl + ((size_t)b * NN + p0) * 1024
    };

    float c[4][4][4] = {};

    // prologue: chunks 0, 1 into stages 0, 1
    #pragma unroll
    for (int pc = 0; pc < 2; ++pc) {
        int c0 = pc * 64;
        unsigned stg = sb + pc * (4 * TS);
        #pragma unroll
        for (int tile = 0; tile < 4; ++tile) {
            unsigned base = stg + tile * TS;
            const __nv_bfloat16* s = srcs[tile];
            #pragma unroll
            for (int rep = 0; rep < 4; ++rep) {
                int u = t + rep * 256;
                int r = u >> 3, q = u & 7;
                cpa16(base + r * 144 + q * 16, s + (size_t)r * 1024 + c0 + q * 8);
            }
        }
        CP_COMMIT();
    }

    for (int ch = 0; ch < 16; ++ch) {
        if (ch + 2 < 16) {
            int c0 = (ch + 2) * 64;
            unsigned stg = sb + ((ch + 2) % 3) * (4 * TS);
            #pragma unroll
            for (int tile = 0; tile < 4; ++tile) {
                unsigned base = stg + tile * TS;
                const __nv_bfloat16* s = srcs[tile];
                #pragma unroll
                for (int rep = 0; rep < 4; ++rep) {
                    int u = t + rep * 256;
                    int r = u >> 3, q = u & 7;
                    cpa16(base + r * 144 + q * 16, s + (size_t)r * 1024 + c0 + q * 8);
                }
            }
            CP_COMMIT();
        }
        if (ch < 14) { CP_WAIT2(); }
        else if (ch == 14) { CP_WAIT1(); }
        else { CP_WAIT0(); }
        __syncthreads();
        unsigned abase = sb + (ch % 3) * (4 * TS);
        unsigned aAddr = abase + (unsigned)((wr * 64 + (lid & 15)) * 144 + (lid >> 4) * 16);
        unsigned bAddr = abase + 2 * TS +
            (unsigned)((wc * 32 + ((lid >> 4) & 1) * 8 + (lid & 7)) * 144 + ((lid >> 3) & 1) * 16);
        #pragma unroll
        for (int ks = 0; ks < 4; ++ks) {
            unsigned bh[2][4], bl[2][4];
            ldsm4(bh[0], bAddr + ks * 32);
            ldsm4(bh[1], bAddr + 16 * 144 + ks * 32);
            ldsm4(bl[0], bAddr + TS + ks * 32);
            ldsm4(bl[1], bAddr + TS + 16 * 144 + ks * 32);
            #pragma unroll
            for (int mt = 0; mt < 4; ++mt) {
                unsigned ah[4], al[4];
                ldsm4(ah, aAddr + mt * 2304 + ks * 32);
                ldsm4(al, aAddr + TS + mt * 2304 + ks * 32);
                #pragma unroll
                for (int nt = 0; nt < 4; ++nt) {
                    const unsigned* bhp = &bh[nt >> 1][(nt & 1) * 2];
                    const unsigned* blp = &bl[nt >> 1][(nt & 1) * 2];
                    mma_bf16(c[mt][nt], ah, bhp);
                    mma_bf16(c[mt][nt], ah, blp);
                    mma_bf16(c[mt][nt], al, bhp);
                }
            }
        }
        __syncthreads();
    }

    int g = lid >> 2, tig = lid & 3;
    if (blockIdx.y == 0) {
        // stage bf16 hi/lo transpose in smem, write QKT; k1 rows also fp32 to g_qk
        __nv_bfloat16* Th = (__nv_bfloat16*)smem;          // [128][136]
        __nv_bfloat16* Tl = Th + 128 * 136;
        #pragma unroll
        for (int mt = 0; mt < 4; ++mt) {
            int jrow = wr * 64 + mt * 16 + g;
            float b0 = g_bqk[jrow], b1 = g_bqk[jrow + 8];
            #pragma unroll
            for (int nt = 0; nt < 4; ++nt) {
                int p = wc * 32 + nt * 8 + tig * 2;
                float v0 = c[mt][nt][0] + b0;
                float v1 = c[mt][nt][1] + b0;
                float v2 = c[mt][nt][2] + b1;
                float v3 = c[mt][nt][3] + b1;
                __nv_bfloat16 h, l;
                split_bf16(v0, h, l); Th[p * 136 + jrow] = h;       Tl[p * 136 + jrow] = l;
                split_bf16(v1, h, l); Th[(p + 1) * 136 + jrow] = h; Tl[(p + 1) * 136 + jrow] = l;
                split_bf16(v2, h, l); Th[p * 136 + jrow + 8] = h;   Tl[p * 136 + jrow + 8] = l;
                split_bf16(v3, h, l); Th[(p + 1) * 136 + jrow + 8] = h; Tl[(p + 1) * 136 + jrow + 8] = l;
                if (wr == 1) {
                    size_t r0 = ((size_t)(b * 128 + jrow)) * NN;
                    size_t r1 = r0 + (size_t)8 * NN;
                    *(float2*)&g_qk[r0 + p0 + p] = {v0, v1};
                    *(float2*)&g_qk[r1 + p0 + p] = {v2, v3};
                }
            }
        }
        __syncthreads();
        #pragma unroll
        for (int rep = 0; rep < 8; ++rep) {
            int u = t + rep * 256;
            int r = u >> 4, q = u & 15;
            size_t dst = ((size_t)(b * NN + p0 + r)) * 128 + q * 8;
            *(uint4*)(g_QKTh + dst) = *(const uint4*)&Th[r * 136 + q * 8];
            *(uint4*)(g_QKTl + dst) = *(const uint4*)&Tl[r * 136 + q * 8];
        }
    } else {
        #pragma unroll
        for (int mt = 0; mt < 4; ++mt) {
            int jl = wr * 64 + mt * 16 + g;
            float b0 = g_bqk[128 + jl], b1 = g_bqk[128 + jl + 8];
            size_t r0 = ((size_t)(b * 128 + jl)) * NN;
            size_t r1 = r0 + (size_t)8 * NN;
            #pragma unroll
            for (int nt = 0; nt < 4; ++nt) {
                int pc = p0 + wc * 32 + nt * 8 + tig * 2;
                __nv_bfloat16 h0, l0, h1, l1;
                split_bf16(c[mt][nt][0] + b0, h0, l0);
                split_bf16(c[mt][nt][1] + b0, h1, l1);
                *(__nv_bfloat162*)&g_CH[r0 + pc] = {h0, h1};
                *(__nv_bfloat162*)&g_CL[r0 + pc] = {l0, l1};
                split_bf16(c[mt][nt][2] + b1, h0, l0);
                split_bf16(c[mt][nt][3] + b1, h1, l1);
                *(__nv_bfloat162*)&g_CH[r1 + pc] = {h0, h1};
                *(__nv_bfloat162*)&g_CL[r1 + pc] = {l0, l1};
            }
        }
    }
}

// ---------------- spatial pass A: 2-pass split ((Qh+Ql)·Kh), Kh-only loads, occ 2 ----------------
#define PAT 18432
#define PA_SMEM (4 * PAT + 2048 + 512)   // 76288 -> 2 CTAs/SM
__global__ void __launch_bounds__(256, 2) passA_tc() {
    extern __shared__ __align__(16) char smem[];
    unsigned sb = smem_u32(smem);
    int t = threadIdx.x;
    int wid = t >> 5, lid = t & 31;
    int b = blockIdx.y;
    int n0 = blockIdx.x * 128;
    int wr = wid & 1;
    int wc = wid >> 1;
    int g = lid >> 2, tig = lid & 3;

    // Q hi/lo resident
    #pragma unroll
    for (int rep = 0; rep < 4; ++rep) {
        int u = t + rep * 256;
        int r = u >> 3, q = u & 7;
        size_t src = ((size_t)b * NN + n0 + r) * 128 + q * 8;
        cpa16(sb + r * 144 + q * 16, g_QKTh + src);
        cpa16(sb + PAT + r * 144 + q * 16, g_QKTl + src);
    }
    // K chunk 0 (hi only) into buf0
    #pragma unroll
    for (int rep = 0; rep < 4; ++rep) {
        int u = t + rep * 256;
        int r = u >> 3, q = u & 7;
        size_t src = ((size_t)b * NN + r) * 128 + 64 + q * 8;
        cpa16(sb + 2 * PAT + r * 144 + q * 16, g_QKTh + src);
    }
    CP_COMMIT();

    unsigned aAddrH = sb + (unsigned)((wr * 64 + (lid & 15)) * 144 + (lid >> 4) * 16);

    float zacc[8] = {};
    size_t ebase = ((size_t)b) << 24;

    for (int ch = 0; ch < 32; ++ch) {
        int m0 = ch * 128;
        if (ch + 1 < 32) {
            unsigned kb = 2 * PAT + ((ch + 1) & 1) * PAT;
            int m1 = (ch + 1) * 128;
            #pragma unroll
            for (int rep = 0; rep < 4; ++rep) {
                int u = t + rep * 256;
                int r = u >> 3, q = u & 7;
                size_t src = ((size_t)b * NN + m1 + r) * 128 + 64 + q * 8;
                cpa16(sb + kb + r * 144 + q * 16, g_QKTh + src);
            }
            CP_COMMIT();
            CP_WAIT1();
        } else {
            CP_WAIT0();
        }
        __syncthreads();
        unsigned kb = 2 * PAT + (ch & 1) * PAT;
        unsigned bAddrH = sb + kb +
            (unsigned)((wc * 32 + ((lid >> 4) & 1) * 8 + (lid & 7)) * 144 + ((lid >> 3) & 1) * 16);
        float c[4][4][4] = {};
        #pragma unroll
        for (int ks = 0; ks < 4; ++ks) {
            unsigned bh[2][4];
            ldsm4(bh[0], bAddrH + ks * 32);
            ldsm4(bh[1], bAddrH + 16 * 144 + ks * 32);
            #pragma unroll
            for (int mt = 0; mt < 4; ++mt) {
                unsigned ah[4], al[4];
                ldsm4(ah, aAddrH + mt * 2304 + ks * 32);
                ldsm4(al, aAddrH + PAT + mt * 2304 + ks * 32);
                #pragma unroll
                for (int nt = 0; nt < 4; ++nt) {
                    const unsigned* bhp = &bh[nt >> 1][(nt & 1) * 2];
                    mma_bf16(c[mt][nt], ah, bhp);
                    mma_bf16(c[mt][nt], al, bhp);
                }
            }
        }
        #pragma unroll
        for (int mt = 0; mt < 4; ++mt) {
            int n = n0 + wr * 64 + mt * 16 + g;
            #pragma unroll
            for (int nt = 0; nt < 4; ++nt) {
                int m = m0 + wc * 32 + nt * 8 + tig * 2;
                float e0, e1, e2, e3;
                fexp2x(c[mt][nt][0], c[mt][nt][1], e0, e1);
                fexp2x(c[mt][nt][2], c[mt][nt][3], e2, e3);
                __nv_bfloat162 v0 = {__float2bfloat16(e0), __float2bfloat16(e1)};
                __nv_bfloat162 v1 = {__float2bfloat16(e2), __float2bfloat16(e3)};
                *(__nv_bfloat162*)&g_E2[ebase + (size_t)n * NN + m] = v0;
                *(__nv_bfloat162*)&g_E2[ebase + (size_t)(n + 8) * NN + m] = v1;
                zacc[mt * 2] += e0 + e1;
                zacc[mt * 2 + 1] += e2 + e3;
            }
        }
        __syncthreads();
    }

    float* zp = (float*)(smem + 4 * PAT);
    float* zsm = (float*)(smem + 4 * PAT + 2048);
    #pragma unroll
    for (int s = 0; s < 8; ++s) {
        float v = zacc[s];
        v += __shfl_xor_sync(0xFFFFFFFF, v, 1);
        v += __shfl_xor_sync(0xFFFFFFFF, v, 2);
        if (tig == 0)
            zp[wc * 128 + wr * 64 + (s >> 1) * 16 + (s & 1) * 8 + g] = v;
    }
    __syncthreads();
    if (t < 128) {
        float s = zp[t] + zp[128 + t] + zp[256 + t] + zp[384 + t];
        float zi = 1.0f / s;
        g_Zinv[b * NN + n0 + t] = zi;
        zsm[t] = zi;
    }
    __syncthreads();

    #pragma unroll
    for (int rep = 0; rep < 8; ++rep) {
        int idx = t + rep * 256;
        int r = idx >> 5;
        int nq = (idx & 31) * 4;
        float4 k4 = *(const float4*)&g_qk[((size_t)(b * 128 + 64 + r)) * NN + n0 + nq];
        float v0 = k4.x * zsm[nq];
        float v1 = k4.y * zsm[nq + 1];
        float v2 = k4.z * zsm[nq + 2];
        float v3 = k4.w * zsm[nq + 3];
        __nv_bfloat16 h0, l0, h1, l1;
        size_t o = ((size_t)b * 64 + r) * NN + n0 + nq;
        split_bf16(v0, h0, l0); split_bf16(v1, h1, l1);
        *(__nv_bfloat162*)&g_KZh[o] = {h0, h1};
        *(__nv_bfloat162*)&g_KZl[o] = {l0, l1};
        split_bf16(v2, h0, l0); split_bf16(v3, h1, l1);
        *(__nv_bfloat162*)&g_KZh[o + 2] = {h0, h1};
        *(__nv_bfloat162*)&g_KZl[o + 2] = {l0, l1};
    }
}

// ---------------- spatial pass B ----------------
#define PBS 35840
#define PB_SMEM (2 * PBS)
__global__ void __launch_bounds__(256, 2) passB_tc() {
    extern __shared__ __align__(16) char smem[];
    unsigned sb = smem_u32(smem);
    int t = threadIdx.x;
    int wid = t >> 5, lid = t & 31;
    int b = blockIdx.y;
    int m0 = blockIdx.x * 128;
    int g = lid >> 2, tig = lid & 3;

    float c[4][2][4] = {};
    size_t ebase = ((size_t)b) << 24;

    {
        #pragma unroll
        for (int rep = 0; rep < 2; ++rep) {
            int u = t + rep * 256;
            int r = u >> 3, q = u & 7;
            size_t src = ((size_t)b * 64 + r) * NN + q * 8;
            cpa16(sb + r * 144 + q * 16, g_KZh + src);
            cpa16(sb + 9216 + r * 144 + q * 16, g_KZl + src);
        }
        #pragma unroll
        for (int rep = 0; rep < 4; ++rep) {
            int u = t + rep * 256;
            int r = u >> 4, q = u & 15;
            cpa16(sb + 18432 + r * 272 + q * 16, g_E2 + ebase + (size_t)r * NN + m0 + q * 8);
        }
        CP_COMMIT();
    }

    for (int ch = 0; ch < 64; ++ch) {
        if (ch + 1 < 64) {
            unsigned boff = ((ch + 1) & 1) * PBS;
            int n1 = (ch + 1) * 64;
            #pragma unroll
            for (int rep = 0; rep < 2; ++rep) {
                int u = t + rep * 256;
                int r = u >> 3, q = u & 7;
                size_t src = ((size_t)b * 64 + r) * NN + n1 + q * 8;
                cpa16(sb + boff + r * 144 + q * 16, g_KZh + src);
                cpa16(sb + boff + 9216 + r * 144 + q * 16, g_KZl + src);
            }
            #pragma unroll
            for (int rep = 0; rep < 4; ++rep) {
                int u = t + rep * 256;
                int r = u >> 4, q = u & 15;
                cpa16(sb + boff + 18432 + r * 272 + q * 16,
                      g_E2 + ebase + (size_t)(n1 + r) * NN + m0 + q * 8);
            }
            CP_COMMIT();
            CP_WAIT1();
        } else {
            CP_WAIT0();
        }
        __syncthreads();
        unsigned boff = (ch & 1) * PBS;
        unsigned aAddrH = sb + boff + (unsigned)(((lid & 15)) * 144 + (lid >> 4) * 16);
        unsigned eAddr = sb + boff + 18432 +
            (unsigned)(((lid & 7) + ((lid >> 3) & 1) * 8) * 272 + (wid * 16 + (lid >> 4) * 8) * 2);
        #pragma unroll
        for (int ks = 0; ks < 4; ++ks) {
            unsigned eb[4];
            ldsm4t(eb, eAddr + ks * 16 * 272);
            #pragma unroll
            for (int mt = 0; mt < 4; ++mt) {
                unsigned ah[4], al[4];
                ldsm4(ah, aAddrH + mt * 2304 + ks * 32);
                ldsm4(al, aAddrH + 9216 + mt * 2304 + ks * 32);
                #pragma unroll
                for (int nt = 0; nt < 2; ++nt) {
                    mma_bf16(c[mt][nt], ah, &eb[nt * 2]);
                    mma_bf16(c[mt][nt], al, &eb[nt * 2]);
                }
            }
        }
        __syncthreads();
    }

    #pragma unroll
    for (int mt = 0; mt < 4; ++mt) {
        int r = mt * 16 + g;
        size_t r0 = ((size_t)(b * 128 + r)) * NN;
        size_t r1 = r0 + (size_t)8 * NN;
        #pragma unroll
        for (int nt = 0; nt < 2; ++nt) {
            int m = m0 + wid * 16 + nt * 8 + tig * 2;
            __nv_bfloat16 h0, l0, h1, l1;
            split_bf16(c[mt][nt][0], h0, l0);
            split_bf16(c[mt][nt][1], h1, l1);
            *(__nv_bfloat162*)&g_OSh[r0 + m] = {h0, h1};
            *(__nv_bfloat162*)&g_OSl[r0 + m] = {l0, l1};
            split_bf16(c[mt][nt][2], h0, l0);
            split_bf16(c[mt][nt][3], h1, l1);
            *(__nv_bfloat162*)&g_OSh[r1 + m] = {h0, h1};
            *(__nv_bfloat162*)&g_OSl[r1 + m] = {l0, l1};
        }
    }
}

// ---------------- channel Gram via HMMA ----------------
__global__ void __launch_bounds__(128) chan_gram_tc() {
    __shared__ __align__(16) char csm[4 * 9216];
    unsigned sb = smem_u32(csm);
    int t = threadIdx.x;
    int wid = t >> 5, lid = t & 31;
    int b = blockIdx.y;
    int chunk = blockIdx.x;
    int wr = wid & 1, wc = wid >> 1;
    int g = lid >> 2, tig = lid & 3;

    unsigned aAddr = sb + (unsigned)((wr * 32 + (lid & 15)) * 144 + (lid >> 4) * 16);
    unsigned bAddr = sb + 2 * 9216 +
        (unsigned)((wc * 32 + ((lid >> 4) & 1) * 8 + (lid & 7)) * 144 + ((lid >> 3) & 1) * 16);

    float c[2][4][4] = {};

    for (int sub = 0; sub < 8; ++sub) {
        int n0 = chunk * 512 + sub * 64;
        __syncthreads();
        #pragma unroll
        for (int rep = 0; rep < 4; ++rep) {
            int u = t + rep * 128;
            int r = u >> 3, q = u & 7;
            size_t sq = ((size_t)(b * 128 + r)) * NN + n0 + q * 8;
            size_t sk = ((size_t)(b * 128 + 64 + r)) * NN + n0 + q * 8;
            *(uint4*)(csm + r * 144 + q * 16) = *(const uint4*)(g_CH + sq);
            *(uint4*)(csm + 9216 + r * 144 + q * 16) = *(const uint4*)(g_CL + sq);
            *(uint4*)(csm + 2 * 9216 + r * 144 + q * 16) = *(const uint4*)(g_CH + sk);
            *(uint4*)(csm + 3 * 9216 + r * 144 + q * 16) = *(const uint4*)(g_CL + sk);
        }
        __syncthreads();
        #pragma unroll
        for (int ks = 0; ks < 4; ++ks) {
            unsigned bh[2][4], bl[2][4];
            ldsm4(bh[0], bAddr + ks * 32);
            ldsm4(bh[1], bAddr + 16 * 144 + ks * 32);
            ldsm4(bl[0], bAddr + 9216 + ks * 32);
            ldsm4(bl[1], bAddr + 9216 + 16 * 144 + ks * 32);
            #pragma unroll
            for (int mt = 0; mt < 2; ++mt) {
                unsigned ah[4], al[4];
                ldsm4(ah, aAddr + mt * 2304 + ks * 32);
                ldsm4(al, aAddr + 9216 + mt * 2304 + ks * 32);
                #pragma unroll
                for (int nt = 0; nt < 4; ++nt) {
                    const unsigned* bhp = &bh[nt >> 1][(nt & 1) * 2];
                    const unsigned* blp = &bl[nt >> 1][(nt & 1) * 2];
                    mma_bf16(c[mt][nt], ah, bhp);
                    mma_bf16(c[mt][nt], ah, blp);
                    mma_bf16(c[mt][nt], al, bhp);
                }
            }
        }
    }

    float* gp = &g_Gp[(b * 8 + chunk) * 4096];
    #pragma unroll
    for (int mt = 0; mt < 2; ++mt) {
        int r = wr * 32 + mt * 16 + g;
        #pragma unroll
        for (int nt = 0; nt < 4; ++nt) {
            int s = wc * 32 + nt * 8 + tig * 2;
            *(float2*)&gp[r * 64 + s] = {c[mt][nt][0], c[mt][nt][1]};
            *(float2*)&gp[(r + 8) * 64 + s] = {c[mt][nt][2], c[mt][nt][3]};
        }
    }
}

__global__ void chan_softmax() {
    int r = blockIdx.x;
    int b = blockIdx.y;
    int s = threadIdx.x;
    __shared__ float red[64];
    float v = 0.f;
    #pragma unroll
    for (int ch = 0; ch < 8; ++ch)
        v += g_Gp[(b * 8 + ch) * 4096 + r * 64 + s];
    red[s] = v;
    __syncthreads();
    for (int off = 32; off >= 1; off >>= 1) {
        if (s < off) red[s] = fmaxf(red[s], red[s + off]);
        __syncthreads();
    }
    float mx = red[0];
    __syncthreads();
    float e = __expf(v - mx);
    red[s] = e;
    __syncthreads();
    for (int off = 32; off >= 1; off >>= 1) {
        if (s < off) red[s] += red[s + off];
        __syncthreads();
    }
    g_A[b * 4096 + r * 64 + s] = e / red[0];
}

__global__ void __launch_bounds__(256) chan_out() {
    int b = blockIdx.y;
    int p = blockIdx.x * 256 + threadIdx.x;
    __shared__ __align__(16) float As[64][64];
    #pragma unroll
    for (int k = 0; k < 16; ++k)
        (&As[0][0])[threadIdx.x + k * 256] = g_A[b * 4096 + threadIdx.x + k * 256];
    __syncthreads();
    float kreg[64];
    #pragma unroll
    for (int s = 0; s < 64; ++s) {
        size_t o = ((size_t)(b * 128 + 64 + s)) * NN + p;
        kreg[s] = __bfloat162float(g_CH[o]) + __bfloat162float(g_CL[o]);
    }
    ull kp2[32];
    #pragma unroll
    for (int s = 0; s < 32; ++s) {
        ull r; asm("mov.b64 %0, {%1, %2};" : "=l"(r) : "f"(kreg[2 * s]), "f"(kreg[2 * s + 1]));
        kp2[s] = r;
    }
    #pragma unroll 2
    for (int r = 0; r < 64; ++r) {
        ull acc = 0;
        const ull* arow = (const ull*)&As[r][0];
        #pragma unroll
        for (int s = 0; s < 32; ++s)
            fma2s(acc, arow[s], kp2[s]);
        float lo, hi;
        unpack2(acc, lo, hi);
        float v = lo + hi;
        __nv_bfloat16 h, l; split_bf16(v, h, l);
        size_t o = ((size_t)(b * 128 + 64 + r)) * NN + p;
        g_OSh[o] = h; g_OSl[o] = l;
    }
}

// ---------------- final GEMM via HMMA (3-pass) ----------------
#define FT_SMEM 139264
__global__ void __launch_bounds__(256) final_tc(float* __restrict__ out) {
    extern __shared__ __align__(16) char smem[];
    unsigned sb = smem_u32(smem);
    int t = threadIdx.x;
    int wid = t >> 5, lid = t & 31;
    int b = blockIdx.z;
    int o0 = blockIdx.y * 128;
    int p0 = blockIdx.x * 128;
    int wr = wid & 1, wc = wid >> 1;
    int g = lid >> 2, tig = lid & 3;

    #pragma unroll
    for (int rep = 0; rep < 8; ++rep) {
        int u = t + rep * 256;
        int r = u >> 4, q = u & 15;
        *(uint4*)(smem + r * 272 + q * 16) = *(const uint4*)(g_WCh + (size_t)(o0 + r) * 128 + q * 8);
        *(uint4*)(smem + 34816 + r * 272 + q * 16) = *(const uint4*)(g_WCl + (size_t)(o0 + r) * 128 + q * 8);
        size_t bs = ((size_t)(b * 128 + r)) * NN + p0 + q * 8;
        *(uint4*)(smem + 69632 + r * 272 + q * 16) = *(const uint4*)(g_OSh + bs);
        *(uint4*)(smem + 104448 + r * 272 + q * 16) = *(const uint4*)(g_OSl + bs);
    }
    __syncthreads();

    unsigned aAddr = sb + (unsigned)((wr * 64 + (lid & 15)) * 272 + (lid >> 4) * 16);
    unsigned eAddr = sb + 69632 +
        (unsigned)(((lid & 7) + ((lid >> 3) & 1) * 8) * 272 + (wc * 32 + (lid >> 4) * 8) * 2);

    float c[4][4][4] = {};
    #pragma unroll
    for (int ks = 0; ks < 8; ++ks) {
        unsigned bh[2][4], bl[2][4];
        ldsm4t(bh[0], eAddr + ks * 16 * 272);
        ldsm4t(bh[1], eAddr + ks * 16 * 272 + 32);
        ldsm4t(bl[0], eAddr + 34816 + ks * 16 * 272);
        ldsm4t(bl[1], eAddr + 34816 + ks * 16 * 272 + 32);
        #pragma unroll
        for (int mt = 0; mt < 4; ++mt) {
            unsigned ah[4], al[4];
            ldsm4(ah, aAddr + mt * 16 * 272 + ks * 32);
            ldsm4(al, aAddr + 34816 + mt * 16 * 272 + ks * 32);
            #pragma unroll
            for (int nt = 0; nt < 4; ++nt) {
                const unsigned* bhp = &bh[nt >> 1][(nt & 1) * 2];
                const unsigned* blp = &bl[nt >> 1][(nt & 1) * 2];
                mma_bf16(c[mt][nt], ah, bhp);
                mma_bf16(c[mt][nt], ah, blp);
                mma_bf16(c[mt][nt], al, bhp);
            }
        }
    }

    #pragma unroll
    for (int mt = 0; mt < 4; ++mt) {
        int o = o0 + wr * 64 + mt * 16 + g;
        float b0 = g_bout[o], b1 = g_bout[o + 8];
        size_t r0 = ((size_t)(b * 512 + o)) * NN;
        size_t r1 = r0 + (size_t)8 * NN;
        #pragma unroll
        for (int nt = 0; nt < 4; ++nt) {
            int pc = p0 + wc * 32 + nt * 8 + tig * 2;
            float2 v0 = {c[mt][nt][0] + b0, c[mt][nt][1] + b0};
            float2 v1 = {c[mt][nt][2] + b1, c[mt][nt][3] + b1};
            *(float2*)&out[r0 + pc] = v0;
            *(float2*)&out[r1 + pc] = v1;
        }
    }
}

// ---------------- launch ----------------
extern "C" void kernel_launch(void* const* d_in, const int* in_sizes, int n_in,
                              void* d_out, int out_size) {
    const float* top  = (const float*)d_in[0];
    const float* bot  = (const float*)d_in[1];
    const float* wt   = (const float*)d_in[2];
    const float* bt   = (const float*)d_in[3];
    const float* wb   = (const float*)d_in[4];
    const float* bb   = (const float*)d_in[5];
    const float* s_w1 = (const float*)d_in[6];
    const float* s_b1 = (const float*)d_in[7];
    const float* s_w2 = (const float*)d_in[8];
    const float* s_b2 = (const float*)d_in[9];
    const float* s_wo = (const float*)d_in[10];
    const float* s_bo = (const float*)d_in[11];
    const float* c_wq = (const float*)d_in[12];
    const float* c_bq = (const float*)d_in[13];
    const float* c_wk = (const float*)d_in[14];
    const float* c_bk = (const float*)d_in[15];
    const float* c_wo = (const float*)d_in[16];
    const float* c_bo = (const float*)d_in[17];
    const float* f_w  = (const float*)d_in[18];
    const float* f_b  = (const float*)d_in[19];
    float* out = (float*)d_out;

    static cudaStream_t s2 = 0;
    static cudaEvent_t evStart = 0, evPre = 0, evQk = 0, evChan = 0;
    if (!s2) {
        cudaStreamCreateWithFlags(&s2, cudaStreamNonBlocking);
        cudaEventCreateWithFlags(&evStart, cudaEventDisableTiming);
        cudaEventCreateWithFlags(&evPre, cudaEventDisableTiming);
        cudaEventCreateWithFlags(&evQk, cudaEventDisableTiming);
        cudaEventCreateWithFlags(&evChan, cudaEventDisableTiming);
        cudaFuncSetAttribute(qk_tc3, cudaFuncAttributeMaxDynamicSharedMemorySize, QK3_SMEM);
        cudaFuncSetAttribute(passA_tc, cudaFuncAttributeMaxDynamicSharedMemorySize, PA_SMEM);
        cudaFuncSetAttribute(passB_tc, cudaFuncAttributeMaxDynamicSharedMemorySize, PB_SMEM);
        cudaFuncSetAttribute(final_tc, cudaFuncAttributeMaxDynamicSharedMemorySize, FT_SMEM);
    }

    cudaEventRecord(evStart, 0);
    cudaStreamWaitEvent(s2, evStart, 0);

    fold_qkw<<<512, 256>>>(wt, wb, s_w1, s_w2, c_wq, c_wk);
    fold_bias<<<1, 512>>>(bt, bb, s_b1, s_b2, c_bq, c_bk, f_w, s_bo, c_bo, f_b,
                          s_w1, s_w2, c_wq, c_wk);
    conv_x<<<dim3(128, 32, 8), dim3(32, 8), 0, s2>>>(top, bot);
    cudaEventRecord(evPre, s2);
    cudaStreamWaitEvent(0, evPre, 0);

    qk_tc3<<<dim3(32, 2, 8), 256, QK3_SMEM>>>();
    cudaEventRecord(evQk, 0);

    cudaStreamWaitEvent(s2, evQk, 0);
    fold_outc<<<256, 256, 0, s2>>>(f_w, s_wo, c_wo);
    chan_gram_tc<<<dim3(8, 8), 128, 0, s2>>>();
    chan_softmax<<<dim3(64, 8), 64, 0, s2>>>();
    chan_out<<<dim3(16, 8), 256, 0, s2>>>();
    cudaEventRecord(evChan, s2);

    passA_tc<<<dim3(32, 8), 256, PA_SMEM>>>();
    passB_tc<<<dim3(32, 8), 256, PB_SMEM>>>();

    cudaStreamWaitEvent(0, evChan, 0);
    final_tc<<<dim3(32, 4, 8), 256, FT_SMEM>>>(out);
}